// round 5
// baseline (speedup 1.0000x reference)
#include <cuda_runtime.h>
#include <math.h>

#define NFFT 4096
#define DDIM 256
#define HDIM 64
#define NB4  4   // BATCH/2 packed complex batches

typedef unsigned long long u64;

// ---------------- device scratch ----------------
__device__ float2 g_tw[NFFT];                 // e^{-2*pi*i*k/N}
__device__ float2 g_Kf[DDIM * NFFT];          // Hermitian kernel spectrum / N
__device__ float2 g_zT[NB4 * DDIM * NFFT];    // packed transposed signals

// ---------------- f32x2 packed helpers ----------------
__device__ __forceinline__ u64 pk2(float a, float b) {
    u64 r; asm("mov.b64 %0,{%1,%2};" : "=l"(r) : "f"(a), "f"(b)); return r;
}
__device__ __forceinline__ void upk2(u64 v, float& a, float& b) {
    asm("mov.b64 {%0,%1},%2;" : "=f"(a), "=f"(b) : "l"(v));
}
__device__ __forceinline__ u64 fma2(u64 a, u64 b, u64 c) {
    u64 d; asm("fma.rn.f32x2 %0,%1,%2,%3;" : "=l"(d) : "l"(a), "l"(b), "l"(c)); return d;
}
__device__ __forceinline__ u64 add2(u64 a, u64 b) {
    u64 d; asm("add.rn.f32x2 %0,%1,%2;" : "=l"(d) : "l"(a), "l"(b)); return d;
}

// ---------------- twiddle table ----------------
__global__ void tw_init_kernel() {
    int k = blockIdx.x * blockDim.x + threadIdx.x;
    if (k < NFFT) {
        double ang = -6.283185307179586476925286766559 * (double)k / (double)NFFT;
        g_tw[k] = make_float2((float)cos(ang), (float)sin(ang));
    }
}

// =====================================================================
// Fused kernel A: blocks [0, 2048)  -> Cauchy/Woodbury Hermitian spectrum
//                 blocks [2048, 6144) -> transpose (B,L,D)->(B4,D,L) packed
// The two halves are independent; one launch lets them co-run on the SMs.
// =====================================================================
__global__ __launch_bounds__(256) void kf_t1_kernel(
    const float* __restrict__ x,
    const float2* __restrict__ lam, const float2* __restrict__ P,
    const float2* __restrict__ B,   const float2* __restrict__ C,
    const float* __restrict__ log_delta)
{
    __shared__ float2 slam[HDIM];
    __shared__ float2 snl[HDIM];
    __shared__ float4 sA[HDIM], sB[HDIM], sC[HDIM];
    __shared__ float2 sW[HDIM];
    __shared__ float2 tile[32][33];

    int tid = threadIdx.x;

    if (blockIdx.x < 2048) {
        // -------- kf path: d in [0,256), part in [0,8) --------
        int d    = blockIdx.x >> 3;
        int part = blockIdx.x & 7;

        if (tid < HDIM) slam[tid] = lam[tid];
        __syncthreads();
        if (tid < HDIM) {
            float2 L = slam[tid];
            float best = 3.4e38f; int bi = tid;
            #pragma unroll 8
            for (int j = 0; j < HDIM; ++j) {
                float2 M = slam[j];
                float dx = M.x - L.x, dy = M.y + L.y;   // |lam_j - conj(lam_h)|^2
                float e = dx * dx + dy * dy;
                if (e < best) { best = e; bi = j; }
            }
            float2 c  = C[(d << 6) + tid];
            float2 c2 = C[(d << 6) | bi];
            float chx = 0.5f * (c.x + c2.x);
            float chy = 0.5f * (c.y - c2.y);           // Chat = (C_h + conj(C_hbar))/2
            float2 b = B[(d << 6) + tid];
            float2 p = P[tid];
            float w00x = chx * b.x - chy * b.y, w00y = chx * b.y + chy * b.x;
            float w01x = chx * p.x - chy * p.y, w01y = chx * p.y + chy * p.x;
            float w10x = p.x * b.x + p.y * b.y, w10y = p.x * b.y - p.y * b.x;
            float w11  = p.x * p.x + p.y * p.y;
            sA[tid] = make_float4(w00x, w00x, -w00y, w00y);
            sB[tid] = make_float4(w01x, w01x, -w01y, w01y);
            sC[tid] = make_float4(w10x, w10x, -w10y, w10y);
            sW[tid] = make_float2(w11, w11);
            snl[tid] = make_float2(-L.x, -L.y);
        }
        __syncthreads();

        float delta = __expf(log_delta[d]);

        // Nyquist bin (z = -1): at = 0.5*delta*sum_h Re(w00)
        if (part == 0 && tid == 0) {
            float s = 0.0f;
            #pragma unroll
            for (int h = 0; h < HDIM; ++h) s += sA[h].x;
            g_Kf[(d << 12) + 2048] = make_float2(0.5f * delta * s * (1.0f / (float)NFFT), 0.0f);
        }

        int l = part * 256 + tid;                  // [0, 2048)
        float2 t = g_tw[l];
        float zr = t.x, zi = -t.y;                 // z = e^{+2*pi*i*l/N}
        float ux = 1.0f + zr, uy = zi;             // u = 1+z (never 0 for l<2048)
        float vx = 2.0f - 2.0f * zr, vy = -2.0f * zi;
        float udx = ux * delta, udy = uy * delta;
        float di = __fdividef(1.0f, udx * udx + udy * udy);
        float gx = (vx * udx + vy * udy) * di;     // g = v/(u*delta)
        float gy = (vy * udx - vx * udy) * di;
        u64 g2 = pk2(gx, gy);

        u64 s00 = 0ull, s01 = 0ull, s10 = 0ull, s11 = 0ull;
        const u64* pnl        = (const u64*)snl;
        const ulonglong2* pA  = (const ulonglong2*)sA;
        const ulonglong2* pB  = (const ulonglong2*)sB;
        const ulonglong2* pC  = (const ulonglong2*)sC;
        const u64* pW         = (const u64*)sW;
        #pragma unroll 16
        for (int h = 0; h < HDIM; ++h) {
            u64 q = add2(g2, pnl[h]);
            float qx, qy; upk2(q, qx, qy);
            float im = __fdividef(1.0f, qx * qx + qy * qy);
            float rr = qx * im, ri = -qy * im;     // 1/(g-lam) = (rr, ri)
            u64 rA = pk2(rr, ri);
            u64 rB = pk2(ri, rr);
            ulonglong2 A = pA[h];  s00 = fma2(A.x, rA, s00); s00 = fma2(A.y, rB, s00);
            ulonglong2 Bv = pB[h]; s01 = fma2(Bv.x, rA, s01); s01 = fma2(Bv.y, rB, s01);
            ulonglong2 Cv = pC[h]; s10 = fma2(Cv.x, rA, s10); s10 = fma2(Cv.y, rB, s10);
            s11 = fma2(pW[h], rA, s11);
        }
        float s00x, s00y, s01x, s01y, s10x, s10y, s11x, s11y;
        upk2(s00, s00x, s00y); upk2(s01, s01x, s01y);
        upk2(s10, s10x, s10y); upk2(s11, s11x, s11y);

        float nx  = s01x * s10x - s01y * s10y;
        float ny  = s01x * s10y + s01y * s10x;
        float dnx = 1.0f + s11x, dny = s11y;
        float ddi = __fdividef(1.0f, dnx * dnx + dny * dny);
        float cx  = (nx * dnx + ny * dny) * ddi;
        float cy  = (ny * dnx - nx * dny) * ddi;
        float k0x = s00x - cx, k0y = s00y - cy;
        float ui  = __fdividef(2.0f, ux * ux + uy * uy);
        float ax  = (k0x * ux + k0y * uy) * ui;
        float ay  = (k0y * ux - k0x * uy) * ui;
        const float sc = 1.0f / (float)NFFT;       // fold 1/N of inverse FFT
        ax *= sc; ay *= sc;
        if (l == 0) ay = 0.0f;
        g_Kf[(d << 12) + l] = make_float2(ax, ay);
        if (l > 0)
            g_Kf[(d << 12) + (NFFT - l)] = make_float2(ax, -ay);
    } else {
        // -------- t1 path: transpose --------
        int m  = blockIdx.x - 2048;
        int b4 = m >> 10;
        int lblk = (m >> 3) & 127;
        int dblk = m & 7;
        int d0 = dblk << 5, l0 = lblk << 5;
        const float4* x4 = (const float4*)x;
        {
            int l = tid >> 3, d4 = tid & 7;
            int base0 = ((b4 * NFFT) + l0 + l) * (DDIM / 4) + (d0 >> 2) + d4;
            int base1 = base0 + 4 * NFFT * (DDIM / 4);
            float4 A  = x4[base0];
            float4 Bv = x4[base1];
            tile[l][4 * d4 + 0] = make_float2(A.x, Bv.x);
            tile[l][4 * d4 + 1] = make_float2(A.y, Bv.y);
            tile[l][4 * d4 + 2] = make_float2(A.z, Bv.z);
            tile[l][4 * d4 + 3] = make_float2(A.w, Bv.w);
        }
        __syncthreads();
        float4* zT4 = (float4*)g_zT;
        #pragma unroll
        for (int u = 0; u < 2; ++u) {
            int mm = tid + (u << 8);
            int dd = mm >> 4, lp = mm & 15;
            float2 t0 = tile[2 * lp][dd];
            float2 t1 = tile[2 * lp + 1][dd];
            zT4[(((b4 * DDIM) + d0 + dd) * NFFT + l0 + 2 * lp) >> 1]
                = make_float4(t0.x, t0.y, t1.x, t1.y);
        }
    }
}

// ---------------- radix-8 Stockham FFT helpers ----------------
__device__ __forceinline__ float2 cmulf(float2 a, float2 b) {
    return make_float2(a.x * b.x - a.y * b.y, a.x * b.y + a.y * b.x);
}
#define SWZ(m) ((m) ^ (((m) >> 4) & 7))

template<int DIR>
__device__ __forceinline__ void bfly8(float2 a[8]) {
    const float S2 = 0.70710678118654752440f;
    float2 b0, b1, b2, b3, c0, c1, c2, c3;
    b0.x=a[0].x+a[4].x; b0.y=a[0].y+a[4].y;  c0.x=a[0].x-a[4].x; c0.y=a[0].y-a[4].y;
    b1.x=a[1].x+a[5].x; b1.y=a[1].y+a[5].y;  c1.x=a[1].x-a[5].x; c1.y=a[1].y-a[5].y;
    b2.x=a[2].x+a[6].x; b2.y=a[2].y+a[6].y;  c2.x=a[2].x-a[6].x; c2.y=a[2].y-a[6].y;
    b3.x=a[3].x+a[7].x; b3.y=a[3].y+a[7].y;  c3.x=a[3].x-a[7].x; c3.y=a[3].y-a[7].y;
    float2 tc1, tc2, tc3;
    if (DIR > 0) {
        tc1 = make_float2(S2 * (c1.x + c1.y),  S2 * (c1.y - c1.x));
        tc2 = make_float2(c2.y, -c2.x);
        tc3 = make_float2(S2 * (c3.y - c3.x), -S2 * (c3.x + c3.y));
    } else {
        tc1 = make_float2(S2 * (c1.x - c1.y),  S2 * (c1.y + c1.x));
        tc2 = make_float2(-c2.y, c2.x);
        tc3 = make_float2(-S2 * (c3.x + c3.y), S2 * (c3.x - c3.y));
    }
    float2 p0 = make_float2(b0.x + b2.x, b0.y + b2.y);
    float2 p1 = make_float2(b0.x - b2.x, b0.y - b2.y);
    float2 p2 = make_float2(b1.x + b3.x, b1.y + b3.y);
    float2 p3 = make_float2(b1.x - b3.x, b1.y - b3.y);
    float2 q0 = make_float2(c0.x + tc2.x, c0.y + tc2.y);
    float2 q1 = make_float2(c0.x - tc2.x, c0.y - tc2.y);
    float2 q2 = make_float2(tc1.x + tc3.x, tc1.y + tc3.y);
    float2 q3 = make_float2(tc1.x - tc3.x, tc1.y - tc3.y);
    float2 jp3 = (DIR > 0) ? make_float2(p3.y, -p3.x) : make_float2(-p3.y, p3.x);
    float2 jq3 = (DIR > 0) ? make_float2(q3.y, -q3.x) : make_float2(-q3.y, q3.x);
    a[0] = make_float2(p0.x + p2.x, p0.y + p2.y);
    a[4] = make_float2(p0.x - p2.x, p0.y - p2.y);
    a[2] = make_float2(p1.x + jp3.x, p1.y + jp3.y);
    a[6] = make_float2(p1.x - jp3.x, p1.y - jp3.y);
    a[1] = make_float2(q0.x + q2.x, q0.y + q2.y);
    a[5] = make_float2(q0.x - q2.x, q0.y - q2.y);
    a[3] = make_float2(q1.x + jq3.x, q1.y + jq3.y);
    a[7] = make_float2(q1.x - jq3.x, q1.y - jq3.y);
}

template<int DIR, int TSH>
__device__ __forceinline__ void stage_tw_store(float2* dst, float2 a[8], int i) {
    const int s = 1 << TSH;
    int ps = (i >> TSH) << TSH;
    if (TSH < 9) {
        #pragma unroll
        for (int k = 1; k < 8; ++k) {
            float2 w = g_tw[k * ps];
            if (DIR < 0) w.y = -w.y;
            a[k] = cmulf(a[k], w);
        }
    }
    int base = (i & (s - 1)) + (ps << 3);
    #pragma unroll
    for (int k = 0; k < 8; ++k) dst[SWZ(base + (k << TSH))] = a[k];
}

__global__ __launch_bounds__(512, 2) void fft_conv8_kernel() {
    extern __shared__ float2 sm[];
    float2* S0 = sm;
    float2* S1 = sm + NFFT;
    int d  = blockIdx.x & (DDIM - 1);
    int i  = threadIdx.x;
    float2* sig = g_zT + (size_t)blockIdx.x * NFFT;
    float2 a[8];

    // ---- forward ----
    #pragma unroll
    for (int j = 0; j < 8; ++j) a[j] = sig[i + j * 512];
    bfly8<1>(a); stage_tw_store<1, 0>(S0, a, i);
    __syncthreads();
    #pragma unroll
    for (int j = 0; j < 8; ++j) a[j] = S0[SWZ(i + j * 512)];
    bfly8<1>(a); stage_tw_store<1, 3>(S1, a, i);
    __syncthreads();
    #pragma unroll
    for (int j = 0; j < 8; ++j) a[j] = S1[SWZ(i + j * 512)];
    bfly8<1>(a); stage_tw_store<1, 6>(S0, a, i);
    __syncthreads();
    #pragma unroll
    for (int j = 0; j < 8; ++j) a[j] = S0[SWZ(i + j * 512)];
    bfly8<1>(a);
    // F3 (TSH=9): no twiddles; a[j] IS natural-order bin (i + j*512).
    {
        const float2* kf = g_Kf + (d << 12);
        #pragma unroll
        for (int j = 0; j < 8; ++j) a[j] = cmulf(a[j], __ldg(&kf[i + j * 512]));
    }
    // ---- inverse ----
    bfly8<-1>(a); stage_tw_store<-1, 0>(S1, a, i);
    __syncthreads();
    #pragma unroll
    for (int j = 0; j < 8; ++j) a[j] = S1[SWZ(i + j * 512)];
    bfly8<-1>(a); stage_tw_store<-1, 3>(S0, a, i);
    __syncthreads();
    #pragma unroll
    for (int j = 0; j < 8; ++j) a[j] = S0[SWZ(i + j * 512)];
    bfly8<-1>(a); stage_tw_store<-1, 6>(S1, a, i);
    __syncthreads();
    #pragma unroll
    for (int j = 0; j < 8; ++j) a[j] = S1[SWZ(i + j * 512)];
    bfly8<-1>(a);
    #pragma unroll
    for (int k = 0; k < 8; ++k) sig[i + k * 512] = a[k];
}

// ---------------- untranspose + split Re/Im + D*x ----------------
__global__ __launch_bounds__(256) void t2_kernel(const float* __restrict__ x,
                                                 const float* __restrict__ Dp,
                                                 float* __restrict__ y) {
    __shared__ float2 tile[32][33];
    int b4 = blockIdx.z;
    int d0 = blockIdx.x << 5, l0 = blockIdx.y << 5;
    int tid = threadIdx.x;
    const float4* zT4 = (const float4*)g_zT;
    #pragma unroll
    for (int u = 0; u < 2; ++u) {
        int m = tid + (u << 8);
        int dd = m >> 4, lp = m & 15;
        float4 v = zT4[(((b4 * DDIM) + d0 + dd) * NFFT + l0 + 2 * lp) >> 1];
        tile[2 * lp][dd]     = make_float2(v.x, v.y);
        tile[2 * lp + 1][dd] = make_float2(v.z, v.w);
    }
    __syncthreads();
    {
        int l = tid >> 3, d4 = tid & 7;
        const float4* x4 = (const float4*)x;
        const float4* D4 = (const float4*)Dp;
        float4 DD = D4[(d0 >> 2) + d4];
        int base0 = ((b4 * NFFT) + l0 + l) * (DDIM / 4) + (d0 >> 2) + d4;
        int base1 = base0 + 4 * NFFT * (DDIM / 4);
        float4 X0 = x4[base0], X1 = x4[base1];
        float2 t0 = tile[l][4 * d4 + 0];
        float2 t1 = tile[l][4 * d4 + 1];
        float2 t2 = tile[l][4 * d4 + 2];
        float2 t3 = tile[l][4 * d4 + 3];
        float4* y4 = (float4*)y;
        y4[base0] = make_float4(t0.x + DD.x * X0.x, t1.x + DD.y * X0.y,
                                t2.x + DD.z * X0.z, t3.x + DD.w * X0.w);
        y4[base1] = make_float4(t0.y + DD.x * X1.x, t1.y + DD.y * X1.y,
                                t2.y + DD.z * X1.z, t3.y + DD.w * X1.w);
    }
}

// ---------------- launcher ----------------
extern "C" void kernel_launch(void* const* d_in, const int* in_sizes, int n_in,
                              void* d_out, int out_size) {
    const float*  x   = (const float*)d_in[0];
    const float2* lam = (const float2*)d_in[1];
    const float2* P   = (const float2*)d_in[2];
    const float2* B   = (const float2*)d_in[3];
    const float2* C   = (const float2*)d_in[4];
    const float*  Dp  = (const float*)d_in[5];
    const float*  ld  = (const float*)d_in[6];
    float* y = (float*)d_out;

    cudaFuncSetAttribute(fft_conv8_kernel,
                         cudaFuncAttributeMaxDynamicSharedMemorySize,
                         2 * NFFT * sizeof(float2));

    tw_init_kernel<<<8, 512>>>();
    kf_t1_kernel<<<2048 + 4096, 256>>>(x, lam, P, B, C, ld);
    fft_conv8_kernel<<<NB4 * DDIM, 512, 2 * NFFT * sizeof(float2)>>>();
    t2_kernel<<<dim3(DDIM / 32, NFFT / 32, NB4), dim3(256)>>>(x, Dp, y);
}

// round 6
// speedup vs baseline: 1.1558x; 1.1558x over previous
#include <cuda_runtime.h>
#include <math.h>

#define NFFT 4096
#define DDIM 256
#define HDIM 64
#define NB4  4   // BATCH/2 packed complex batches

typedef unsigned long long u64;

// ---------------- device scratch ----------------
__device__ float2 g_tw[NFFT];                 // e^{-2*pi*i*k/N}
__device__ float2 g_Kf[DDIM * NFFT];          // Hermitian (kernel+D) spectrum / N
__device__ float2 g_zT[NB4 * DDIM * NFFT];    // packed transposed signals

// ---------------- f32x2 packed helpers ----------------
__device__ __forceinline__ u64 pk2(float a, float b) {
    u64 r; asm("mov.b64 %0,{%1,%2};" : "=l"(r) : "f"(a), "f"(b)); return r;
}
__device__ __forceinline__ void upk2(u64 v, float& a, float& b) {
    asm("mov.b64 {%0,%1},%2;" : "=f"(a), "=f"(b) : "l"(v));
}
__device__ __forceinline__ u64 fma2(u64 a, u64 b, u64 c) {
    u64 d; asm("fma.rn.f32x2 %0,%1,%2,%3;" : "=l"(d) : "l"(a), "l"(b), "l"(c)); return d;
}
__device__ __forceinline__ u64 add2(u64 a, u64 b) {
    u64 d; asm("add.rn.f32x2 %0,%1,%2;" : "=l"(d) : "l"(a), "l"(b)); return d;
}

// ---------------- twiddle table ----------------
__global__ void tw_init_kernel() {
    int k = blockIdx.x * blockDim.x + threadIdx.x;
    if (k < NFFT) {
        double ang = -6.283185307179586476925286766559 * (double)k / (double)NFFT;
        g_tw[k] = make_float2((float)cos(ang), (float)sin(ang));
    }
}

// =====================================================================
// Fused kernel A: blocks [0, 2048)   -> Cauchy/Woodbury spectrum (+ D/N fold)
//                 blocks [2048,6144) -> transpose (B,L,D)->(B4,D,L) packed
// =====================================================================
__global__ __launch_bounds__(256) void kf_t1_kernel(
    const float* __restrict__ x,
    const float2* __restrict__ lam, const float2* __restrict__ P,
    const float2* __restrict__ B,   const float2* __restrict__ C,
    const float* __restrict__ log_delta, const float* __restrict__ Dp)
{
    __shared__ float2 slam[HDIM];
    __shared__ float2 snl[HDIM];
    __shared__ float4 sA[HDIM], sB[HDIM], sC[HDIM];
    __shared__ float2 sW[HDIM];
    __shared__ float2 tile[32][33];

    int tid = threadIdx.x;

    if (blockIdx.x < 2048) {
        // -------- kf path: d in [0,256), part in [0,8) --------
        int d    = blockIdx.x >> 3;
        int part = blockIdx.x & 7;

        if (tid < HDIM) slam[tid] = lam[tid];
        __syncthreads();
        if (tid < HDIM) {
            float2 L = slam[tid];
            float best = 3.4e38f; int bi = tid;
            #pragma unroll 8
            for (int j = 0; j < HDIM; ++j) {
                float2 M = slam[j];
                float dx = M.x - L.x, dy = M.y + L.y;   // |lam_j - conj(lam_h)|^2
                float e = dx * dx + dy * dy;
                if (e < best) { best = e; bi = j; }
            }
            float2 c  = C[(d << 6) + tid];
            float2 c2 = C[(d << 6) | bi];
            float chx = 0.5f * (c.x + c2.x);
            float chy = 0.5f * (c.y - c2.y);           // Chat = (C_h + conj(C_hbar))/2
            float2 b = B[(d << 6) + tid];
            float2 p = P[tid];
            float w00x = chx * b.x - chy * b.y, w00y = chx * b.y + chy * b.x;
            float w01x = chx * p.x - chy * p.y, w01y = chx * p.y + chy * p.x;
            float w10x = p.x * b.x + p.y * b.y, w10y = p.x * b.y - p.y * b.x;
            float w11  = p.x * p.x + p.y * p.y;
            sA[tid] = make_float4(w00x, w00x, -w00y, w00y);
            sB[tid] = make_float4(w01x, w01x, -w01y, w01y);
            sC[tid] = make_float4(w10x, w10x, -w10y, w10y);
            sW[tid] = make_float2(w11, w11);
            snl[tid] = make_float2(-L.x, -L.y);
        }
        __syncthreads();

        float delta = __expf(log_delta[d]);
        const float sc = 1.0f / (float)NFFT;       // fold 1/N of inverse FFT
        float dsc = Dp[d] * sc;                    // D*x folded: Kf += D/N at every bin

        // Nyquist bin (z = -1): at = 0.5*delta*sum_h Re(w00)
        if (part == 0 && tid == 0) {
            float s = 0.0f;
            #pragma unroll
            for (int h = 0; h < HDIM; ++h) s += sA[h].x;
            g_Kf[(d << 12) + 2048] = make_float2(0.5f * delta * s * sc + dsc, 0.0f);
        }

        int l = part * 256 + tid;                  // [0, 2048)
        float2 t = g_tw[l];
        float zr = t.x, zi = -t.y;                 // z = e^{+2*pi*i*l/N}
        float ux = 1.0f + zr, uy = zi;             // u = 1+z (never 0 for l<2048)
        float vx = 2.0f - 2.0f * zr, vy = -2.0f * zi;
        float udx = ux * delta, udy = uy * delta;
        float di = __fdividef(1.0f, udx * udx + udy * udy);
        float gx = (vx * udx + vy * udy) * di;     // g = v/(u*delta)
        float gy = (vy * udx - vx * udy) * di;
        u64 g2 = pk2(gx, gy);

        u64 s00 = 0ull, s01 = 0ull, s10 = 0ull, s11 = 0ull;
        const u64* pnl        = (const u64*)snl;
        const ulonglong2* pA  = (const ulonglong2*)sA;
        const ulonglong2* pB  = (const ulonglong2*)sB;
        const ulonglong2* pC  = (const ulonglong2*)sC;
        const u64* pW         = (const u64*)sW;
        #pragma unroll 16
        for (int h = 0; h < HDIM; ++h) {
            u64 q = add2(g2, pnl[h]);
            float qx, qy; upk2(q, qx, qy);
            float im = __fdividef(1.0f, qx * qx + qy * qy);
            float rr = qx * im, ri = -qy * im;     // 1/(g-lam) = (rr, ri)
            u64 rA = pk2(rr, ri);
            u64 rB = pk2(ri, rr);
            ulonglong2 A = pA[h];  s00 = fma2(A.x, rA, s00); s00 = fma2(A.y, rB, s00);
            ulonglong2 Bv = pB[h]; s01 = fma2(Bv.x, rA, s01); s01 = fma2(Bv.y, rB, s01);
            ulonglong2 Cv = pC[h]; s10 = fma2(Cv.x, rA, s10); s10 = fma2(Cv.y, rB, s10);
            s11 = fma2(pW[h], rA, s11);
        }
        float s00x, s00y, s01x, s01y, s10x, s10y, s11x, s11y;
        upk2(s00, s00x, s00y); upk2(s01, s01x, s01y);
        upk2(s10, s10x, s10y); upk2(s11, s11x, s11y);

        float nx  = s01x * s10x - s01y * s10y;
        float ny  = s01x * s10y + s01y * s10x;
        float dnx = 1.0f + s11x, dny = s11y;
        float ddi = __fdividef(1.0f, dnx * dnx + dny * dny);
        float cx  = (nx * dnx + ny * dny) * ddi;
        float cy  = (ny * dnx - nx * dny) * ddi;
        float k0x = s00x - cx, k0y = s00y - cy;
        float ui  = __fdividef(2.0f, ux * ux + uy * uy);
        float ax  = (k0x * ux + k0y * uy) * ui;
        float ay  = (k0y * ux - k0x * uy) * ui;
        ax = ax * sc + dsc; ay *= sc;
        if (l == 0) ay = 0.0f;
        g_Kf[(d << 12) + l] = make_float2(ax, ay);
        if (l > 0)
            g_Kf[(d << 12) + (NFFT - l)] = make_float2(ax, -ay);
    } else {
        // -------- t1 path: transpose --------
        int m  = blockIdx.x - 2048;
        int b4 = m >> 10;
        int lblk = (m >> 3) & 127;
        int dblk = m & 7;
        int d0 = dblk << 5, l0 = lblk << 5;
        const float4* x4 = (const float4*)x;
        {
            int l = tid >> 3, d4 = tid & 7;
            int base0 = ((b4 * NFFT) + l0 + l) * (DDIM / 4) + (d0 >> 2) + d4;
            int base1 = base0 + 4 * NFFT * (DDIM / 4);
            float4 A  = x4[base0];
            float4 Bv = x4[base1];
            tile[l][4 * d4 + 0] = make_float2(A.x, Bv.x);
            tile[l][4 * d4 + 1] = make_float2(A.y, Bv.y);
            tile[l][4 * d4 + 2] = make_float2(A.z, Bv.z);
            tile[l][4 * d4 + 3] = make_float2(A.w, Bv.w);
        }
        __syncthreads();
        float4* zT4 = (float4*)g_zT;
        #pragma unroll
        for (int u = 0; u < 2; ++u) {
            int mm = tid + (u << 8);
            int dd = mm >> 4, lp = mm & 15;
            float2 t0 = tile[2 * lp][dd];
            float2 t1 = tile[2 * lp + 1][dd];
            zT4[(((b4 * DDIM) + d0 + dd) * NFFT + l0 + 2 * lp) >> 1]
                = make_float4(t0.x, t0.y, t1.x, t1.y);
        }
    }
}

// ---------------- radix-8 Stockham FFT helpers ----------------
__device__ __forceinline__ float2 cmulf(float2 a, float2 b) {
    return make_float2(a.x * b.x - a.y * b.y, a.x * b.y + a.y * b.x);
}
#define SWZ(m) ((m) ^ (((m) >> 4) & 7))

template<int DIR>
__device__ __forceinline__ void bfly8(float2 a[8]) {
    const float S2 = 0.70710678118654752440f;
    float2 b0, b1, b2, b3, c0, c1, c2, c3;
    b0.x=a[0].x+a[4].x; b0.y=a[0].y+a[4].y;  c0.x=a[0].x-a[4].x; c0.y=a[0].y-a[4].y;
    b1.x=a[1].x+a[5].x; b1.y=a[1].y+a[5].y;  c1.x=a[1].x-a[5].x; c1.y=a[1].y-a[5].y;
    b2.x=a[2].x+a[6].x; b2.y=a[2].y+a[6].y;  c2.x=a[2].x-a[6].x; c2.y=a[2].y-a[6].y;
    b3.x=a[3].x+a[7].x; b3.y=a[3].y+a[7].y;  c3.x=a[3].x-a[7].x; c3.y=a[3].y-a[7].y;
    float2 tc1, tc2, tc3;
    if (DIR > 0) {
        tc1 = make_float2(S2 * (c1.x + c1.y),  S2 * (c1.y - c1.x));
        tc2 = make_float2(c2.y, -c2.x);
        tc3 = make_float2(S2 * (c3.y - c3.x), -S2 * (c3.x + c3.y));
    } else {
        tc1 = make_float2(S2 * (c1.x - c1.y),  S2 * (c1.y + c1.x));
        tc2 = make_float2(-c2.y, c2.x);
        tc3 = make_float2(-S2 * (c3.x + c3.y), S2 * (c3.x - c3.y));
    }
    float2 p0 = make_float2(b0.x + b2.x, b0.y + b2.y);
    float2 p1 = make_float2(b0.x - b2.x, b0.y - b2.y);
    float2 p2 = make_float2(b1.x + b3.x, b1.y + b3.y);
    float2 p3 = make_float2(b1.x - b3.x, b1.y - b3.y);
    float2 q0 = make_float2(c0.x + tc2.x, c0.y + tc2.y);
    float2 q1 = make_float2(c0.x - tc2.x, c0.y - tc2.y);
    float2 q2 = make_float2(tc1.x + tc3.x, tc1.y + tc3.y);
    float2 q3 = make_float2(tc1.x - tc3.x, tc1.y - tc3.y);
    float2 jp3 = (DIR > 0) ? make_float2(p3.y, -p3.x) : make_float2(-p3.y, p3.x);
    float2 jq3 = (DIR > 0) ? make_float2(q3.y, -q3.x) : make_float2(-q3.y, q3.x);
    a[0] = make_float2(p0.x + p2.x, p0.y + p2.y);
    a[4] = make_float2(p0.x - p2.x, p0.y - p2.y);
    a[2] = make_float2(p1.x + jp3.x, p1.y + jp3.y);
    a[6] = make_float2(p1.x - jp3.x, p1.y - jp3.y);
    a[1] = make_float2(q0.x + q2.x, q0.y + q2.y);
    a[5] = make_float2(q0.x - q2.x, q0.y - q2.y);
    a[3] = make_float2(q1.x + jq3.x, q1.y + jq3.y);
    a[7] = make_float2(q1.x - jq3.x, q1.y - jq3.y);
}

// twiddle via single load + power chain (log depth): w^k, k=1..7
template<int DIR, int TSH>
__device__ __forceinline__ void stage_tw_store(float2* dst, float2 a[8], int i) {
    const int s = 1 << TSH;
    int ps = (i >> TSH) << TSH;
    if (TSH < 9) {
        float2 w1 = g_tw[ps];
        if (DIR < 0) w1.y = -w1.y;
        float2 w2 = cmulf(w1, w1);
        float2 w3 = cmulf(w2, w1);
        float2 w4 = cmulf(w2, w2);
        float2 w5 = cmulf(w3, w2);
        float2 w6 = cmulf(w3, w3);
        float2 w7 = cmulf(w4, w3);
        a[1] = cmulf(a[1], w1);
        a[2] = cmulf(a[2], w2);
        a[3] = cmulf(a[3], w3);
        a[4] = cmulf(a[4], w4);
        a[5] = cmulf(a[5], w5);
        a[6] = cmulf(a[6], w6);
        a[7] = cmulf(a[7], w7);
    }
    int base = (i & (s - 1)) + (ps << 3);
    #pragma unroll
    for (int k = 0; k < 8; ++k) dst[SWZ(base + (k << TSH))] = a[k];
}

__global__ __launch_bounds__(512, 2) void fft_conv8_kernel() {
    extern __shared__ float2 sm[];
    float2* S0 = sm;
    float2* S1 = sm + NFFT;
    int d  = blockIdx.x & (DDIM - 1);
    int i  = threadIdx.x;
    float2* sig = g_zT + (size_t)blockIdx.x * NFFT;
    float2 a[8];

    // ---- forward ----
    #pragma unroll
    for (int j = 0; j < 8; ++j) a[j] = sig[i + j * 512];
    bfly8<1>(a); stage_tw_store<1, 0>(S0, a, i);
    __syncthreads();
    #pragma unroll
    for (int j = 0; j < 8; ++j) a[j] = S0[SWZ(i + j * 512)];
    bfly8<1>(a); stage_tw_store<1, 3>(S1, a, i);
    __syncthreads();
    #pragma unroll
    for (int j = 0; j < 8; ++j) a[j] = S1[SWZ(i + j * 512)];
    bfly8<1>(a); stage_tw_store<1, 6>(S0, a, i);
    __syncthreads();
    #pragma unroll
    for (int j = 0; j < 8; ++j) a[j] = S0[SWZ(i + j * 512)];
    bfly8<1>(a);
    // F3 (TSH=9): no twiddles; a[j] IS natural-order bin (i + j*512).
    {
        const float2* kf = g_Kf + (d << 12);
        #pragma unroll
        for (int j = 0; j < 8; ++j) a[j] = cmulf(a[j], __ldg(&kf[i + j * 512]));
    }
    // ---- inverse ----
    bfly8<-1>(a); stage_tw_store<-1, 0>(S1, a, i);
    __syncthreads();
    #pragma unroll
    for (int j = 0; j < 8; ++j) a[j] = S1[SWZ(i + j * 512)];
    bfly8<-1>(a); stage_tw_store<-1, 3>(S0, a, i);
    __syncthreads();
    #pragma unroll
    for (int j = 0; j < 8; ++j) a[j] = S0[SWZ(i + j * 512)];
    bfly8<-1>(a); stage_tw_store<-1, 6>(S1, a, i);
    __syncthreads();
    #pragma unroll
    for (int j = 0; j < 8; ++j) a[j] = S1[SWZ(i + j * 512)];
    bfly8<-1>(a);
    #pragma unroll
    for (int k = 0; k < 8; ++k) sig[i + k * 512] = a[k];
}

// ---------------- untranspose + split Re/Im (D*x already folded in Kf) -------
__global__ __launch_bounds__(256) void t2_kernel(float* __restrict__ y) {
    __shared__ float2 tile[32][33];
    int b4 = blockIdx.z;
    int d0 = blockIdx.x << 5, l0 = blockIdx.y << 5;
    int tid = threadIdx.x;
    const float4* zT4 = (const float4*)g_zT;
    #pragma unroll
    for (int u = 0; u < 2; ++u) {
        int m = tid + (u << 8);
        int dd = m >> 4, lp = m & 15;
        float4 v = zT4[(((b4 * DDIM) + d0 + dd) * NFFT + l0 + 2 * lp) >> 1];
        tile[2 * lp][dd]     = make_float2(v.x, v.y);
        tile[2 * lp + 1][dd] = make_float2(v.z, v.w);
    }
    __syncthreads();
    {
        int l = tid >> 3, d4 = tid & 7;
        int base0 = ((b4 * NFFT) + l0 + l) * (DDIM / 4) + (d0 >> 2) + d4;
        int base1 = base0 + 4 * NFFT * (DDIM / 4);
        float2 t0 = tile[l][4 * d4 + 0];
        float2 t1 = tile[l][4 * d4 + 1];
        float2 t2 = tile[l][4 * d4 + 2];
        float2 t3 = tile[l][4 * d4 + 3];
        float4* y4 = (float4*)y;
        y4[base0] = make_float4(t0.x, t1.x, t2.x, t3.x);
        y4[base1] = make_float4(t0.y, t1.y, t2.y, t3.y);
    }
}

// ---------------- launcher ----------------
extern "C" void kernel_launch(void* const* d_in, const int* in_sizes, int n_in,
                              void* d_out, int out_size) {
    const float*  x   = (const float*)d_in[0];
    const float2* lam = (const float2*)d_in[1];
    const float2* P   = (const float2*)d_in[2];
    const float2* B   = (const float2*)d_in[3];
    const float2* C   = (const float2*)d_in[4];
    const float*  Dp  = (const float*)d_in[5];
    const float*  ld  = (const float*)d_in[6];
    float* y = (float*)d_out;

    cudaFuncSetAttribute(fft_conv8_kernel,
                         cudaFuncAttributeMaxDynamicSharedMemorySize,
                         2 * NFFT * sizeof(float2));

    tw_init_kernel<<<8, 512>>>();
    kf_t1_kernel<<<2048 + 4096, 256>>>(x, lam, P, B, C, ld, Dp);
    fft_conv8_kernel<<<NB4 * DDIM, 512, 2 * NFFT * sizeof(float2)>>>();
    t2_kernel<<<dim3(DDIM / 32, NFFT / 32, NB4), dim3(256)>>>(y);
}

// round 7
// speedup vs baseline: 1.2319x; 1.0658x over previous
#include <cuda_runtime.h>
#include <math.h>

#define NFFT 4096
#define DDIM 256
#define HDIM 64
#define NB4  4   // BATCH/2 packed complex batches

typedef unsigned long long u64;

// ---------------- device scratch ----------------
__device__ float2 g_tw[NFFT];                 // e^{-2*pi*i*k/N}
__device__ float2 g_Kf[DDIM * NFFT];          // Hermitian (kernel+D) spectrum / N
__device__ float2 g_zT[NB4 * DDIM * NFFT];    // packed transposed signals

// ---------------- f32x2 packed helpers ----------------
__device__ __forceinline__ u64 pk2(float a, float b) {
    u64 r; asm("mov.b64 %0,{%1,%2};" : "=l"(r) : "f"(a), "f"(b)); return r;
}
__device__ __forceinline__ void upk2(u64 v, float& a, float& b) {
    asm("mov.b64 {%0,%1},%2;" : "=f"(a), "=f"(b) : "l"(v));
}
__device__ __forceinline__ u64 fma2(u64 a, u64 b, u64 c) {
    u64 d; asm("fma.rn.f32x2 %0,%1,%2,%3;" : "=l"(d) : "l"(a), "l"(b), "l"(c)); return d;
}
__device__ __forceinline__ u64 add2(u64 a, u64 b) {
    u64 d; asm("add.rn.f32x2 %0,%1,%2;" : "=l"(d) : "l"(a), "l"(b)); return d;
}

// =====================================================================
// Fused kernel A: blocks [0, 2048)    -> Cauchy/Woodbury spectrum (+ D/N fold)
//                 blocks [2048, 6144) -> transpose (B,L,D)->(B4,D,L) packed
//                 blocks [6144, 6160) -> twiddle table (consumed by NEXT launch)
// =====================================================================
__global__ __launch_bounds__(256) void kf_t1_kernel(
    const float* __restrict__ x,
    const float2* __restrict__ lam, const float2* __restrict__ P,
    const float2* __restrict__ B,   const float2* __restrict__ C,
    const float* __restrict__ log_delta, const float* __restrict__ Dp)
{
    __shared__ float2 slam[HDIM];
    __shared__ float2 snl[HDIM];
    __shared__ float4 sA[HDIM], sB[HDIM], sC[HDIM];
    __shared__ float2 sW[HDIM];
    __shared__ float2 tile[32][33];

    int tid = threadIdx.x;

    if (blockIdx.x < 2048) {
        // -------- kf path: d in [0,256), part in [0,8) --------
        int d    = blockIdx.x >> 3;
        int part = blockIdx.x & 7;

        if (tid < HDIM) slam[tid] = lam[tid];
        __syncthreads();
        if (tid < HDIM) {
            float2 L = slam[tid];
            float best = 3.4e38f; int bi = tid;
            #pragma unroll 8
            for (int j = 0; j < HDIM; ++j) {
                float2 M = slam[j];
                float dx = M.x - L.x, dy = M.y + L.y;   // |lam_j - conj(lam_h)|^2
                float e = dx * dx + dy * dy;
                if (e < best) { best = e; bi = j; }
            }
            float2 c  = C[(d << 6) + tid];
            float2 c2 = C[(d << 6) | bi];
            float chx = 0.5f * (c.x + c2.x);
            float chy = 0.5f * (c.y - c2.y);           // Chat = (C_h + conj(C_hbar))/2
            float2 b = B[(d << 6) + tid];
            float2 p = P[tid];
            float w00x = chx * b.x - chy * b.y, w00y = chx * b.y + chy * b.x;
            float w01x = chx * p.x - chy * p.y, w01y = chx * p.y + chy * p.x;
            float w10x = p.x * b.x + p.y * b.y, w10y = p.x * b.y - p.y * b.x;
            float w11  = p.x * p.x + p.y * p.y;
            sA[tid] = make_float4(w00x, w00x, -w00y, w00y);
            sB[tid] = make_float4(w01x, w01x, -w01y, w01y);
            sC[tid] = make_float4(w10x, w10x, -w10y, w10y);
            sW[tid] = make_float2(w11, w11);
            snl[tid] = make_float2(-L.x, -L.y);
        }
        __syncthreads();

        float delta = __expf(log_delta[d]);
        const float sc = 1.0f / (float)NFFT;       // fold 1/N of inverse FFT
        float dsc = Dp[d] * sc;                    // D*x folded: Kf += D/N at every bin

        // Nyquist bin (z = -1): at = 0.5*delta*sum_h Re(w00)
        if (part == 0 && tid == 0) {
            float s = 0.0f;
            #pragma unroll
            for (int h = 0; h < HDIM; ++h) s += sA[h].x;
            g_Kf[(d << 12) + 2048] = make_float2(0.5f * delta * s * sc + dsc, 0.0f);
        }

        int l = part * 256 + tid;                  // [0, 2048)
        // z = e^{+2*pi*i*l/N}; l/2048 is dyadic-exact -> sincospif is exact-arg
        float zr, zi;
        sincospif((float)l * (1.0f / 2048.0f), &zi, &zr);
        float ux = 1.0f + zr, uy = zi;             // u = 1+z (never 0 for l<2048)
        float vx = 2.0f - 2.0f * zr, vy = -2.0f * zi;
        float udx = ux * delta, udy = uy * delta;
        float di = __fdividef(1.0f, udx * udx + udy * udy);
        float gx = (vx * udx + vy * udy) * di;     // g = v/(u*delta)
        float gy = (vy * udx - vx * udy) * di;
        u64 g2 = pk2(gx, gy);

        u64 s00 = 0ull, s01 = 0ull, s10 = 0ull, s11 = 0ull;
        const u64* pnl        = (const u64*)snl;
        const ulonglong2* pA  = (const ulonglong2*)sA;
        const ulonglong2* pB  = (const ulonglong2*)sB;
        const ulonglong2* pC  = (const ulonglong2*)sC;
        const u64* pW         = (const u64*)sW;
        #pragma unroll 16
        for (int h = 0; h < HDIM; ++h) {
            u64 q = add2(g2, pnl[h]);
            float qx, qy; upk2(q, qx, qy);
            float im = __fdividef(1.0f, qx * qx + qy * qy);
            float rr = qx * im, ri = -qy * im;     // 1/(g-lam) = (rr, ri)
            u64 rA = pk2(rr, ri);
            u64 rB = pk2(ri, rr);
            ulonglong2 A = pA[h];  s00 = fma2(A.x, rA, s00); s00 = fma2(A.y, rB, s00);
            ulonglong2 Bv = pB[h]; s01 = fma2(Bv.x, rA, s01); s01 = fma2(Bv.y, rB, s01);
            ulonglong2 Cv = pC[h]; s10 = fma2(Cv.x, rA, s10); s10 = fma2(Cv.y, rB, s10);
            s11 = fma2(pW[h], rA, s11);
        }
        float s00x, s00y, s01x, s01y, s10x, s10y, s11x, s11y;
        upk2(s00, s00x, s00y); upk2(s01, s01x, s01y);
        upk2(s10, s10x, s10y); upk2(s11, s11x, s11y);

        float nx  = s01x * s10x - s01y * s10y;
        float ny  = s01x * s10y + s01y * s10x;
        float dnx = 1.0f + s11x, dny = s11y;
        float ddi = __fdividef(1.0f, dnx * dnx + dny * dny);
        float cx  = (nx * dnx + ny * dny) * ddi;
        float cy  = (ny * dnx - nx * dny) * ddi;
        float k0x = s00x - cx, k0y = s00y - cy;
        float ui  = __fdividef(2.0f, ux * ux + uy * uy);
        float ax  = (k0x * ux + k0y * uy) * ui;
        float ay  = (k0y * ux - k0x * uy) * ui;
        ax = ax * sc + dsc; ay *= sc;
        if (l == 0) ay = 0.0f;
        g_Kf[(d << 12) + l] = make_float2(ax, ay);
        if (l > 0)
            g_Kf[(d << 12) + (NFFT - l)] = make_float2(ax, -ay);
    } else if (blockIdx.x < 6144) {
        // -------- t1 path: transpose --------
        int m  = blockIdx.x - 2048;
        int b4 = m >> 10;
        int lblk = (m >> 3) & 127;
        int dblk = m & 7;
        int d0 = dblk << 5, l0 = lblk << 5;
        const float4* x4 = (const float4*)x;
        {
            int l = tid >> 3, d4 = tid & 7;
            int base0 = ((b4 * NFFT) + l0 + l) * (DDIM / 4) + (d0 >> 2) + d4;
            int base1 = base0 + 4 * NFFT * (DDIM / 4);
            float4 A  = x4[base0];
            float4 Bv = x4[base1];
            tile[l][4 * d4 + 0] = make_float2(A.x, Bv.x);
            tile[l][4 * d4 + 1] = make_float2(A.y, Bv.y);
            tile[l][4 * d4 + 2] = make_float2(A.z, Bv.z);
            tile[l][4 * d4 + 3] = make_float2(A.w, Bv.w);
        }
        __syncthreads();
        float4* zT4 = (float4*)g_zT;
        #pragma unroll
        for (int u = 0; u < 2; ++u) {
            int mm = tid + (u << 8);
            int dd = mm >> 4, lp = mm & 15;
            float2 t0 = tile[2 * lp][dd];
            float2 t1 = tile[2 * lp + 1][dd];
            zT4[(((b4 * DDIM) + d0 + dd) * NFFT + l0 + 2 * lp) >> 1]
                = make_float4(t0.x, t0.y, t1.x, t1.y);
        }
    } else {
        // -------- twiddle table (used by the NEXT launch only) --------
        int k = (blockIdx.x - 6144) * 256 + tid;
        double ang = -6.283185307179586476925286766559 * (double)k / (double)NFFT;
        g_tw[k] = make_float2((float)cos(ang), (float)sin(ang));
    }
}

// ---------------- radix-8 Stockham FFT helpers ----------------
__device__ __forceinline__ float2 cmulf(float2 a, float2 b) {
    return make_float2(a.x * b.x - a.y * b.y, a.x * b.y + a.y * b.x);
}
#define SWZ(m) ((m) ^ (((m) >> 4) & 7))

template<int DIR>
__device__ __forceinline__ void bfly8(float2 a[8]) {
    const float S2 = 0.70710678118654752440f;
    float2 b0, b1, b2, b3, c0, c1, c2, c3;
    b0.x=a[0].x+a[4].x; b0.y=a[0].y+a[4].y;  c0.x=a[0].x-a[4].x; c0.y=a[0].y-a[4].y;
    b1.x=a[1].x+a[5].x; b1.y=a[1].y+a[5].y;  c1.x=a[1].x-a[5].x; c1.y=a[1].y-a[5].y;
    b2.x=a[2].x+a[6].x; b2.y=a[2].y+a[6].y;  c2.x=a[2].x-a[6].x; c2.y=a[2].y-a[6].y;
    b3.x=a[3].x+a[7].x; b3.y=a[3].y+a[7].y;  c3.x=a[3].x-a[7].x; c3.y=a[3].y-a[7].y;
    float2 tc1, tc2, tc3;
    if (DIR > 0) {
        tc1 = make_float2(S2 * (c1.x + c1.y),  S2 * (c1.y - c1.x));
        tc2 = make_float2(c2.y, -c2.x);
        tc3 = make_float2(S2 * (c3.y - c3.x), -S2 * (c3.x + c3.y));
    } else {
        tc1 = make_float2(S2 * (c1.x - c1.y),  S2 * (c1.y + c1.x));
        tc2 = make_float2(-c2.y, c2.x);
        tc3 = make_float2(-S2 * (c3.x + c3.y), S2 * (c3.x - c3.y));
    }
    float2 p0 = make_float2(b0.x + b2.x, b0.y + b2.y);
    float2 p1 = make_float2(b0.x - b2.x, b0.y - b2.y);
    float2 p2 = make_float2(b1.x + b3.x, b1.y + b3.y);
    float2 p3 = make_float2(b1.x - b3.x, b1.y - b3.y);
    float2 q0 = make_float2(c0.x + tc2.x, c0.y + tc2.y);
    float2 q1 = make_float2(c0.x - tc2.x, c0.y - tc2.y);
    float2 q2 = make_float2(tc1.x + tc3.x, tc1.y + tc3.y);
    float2 q3 = make_float2(tc1.x - tc3.x, tc1.y - tc3.y);
    float2 jp3 = (DIR > 0) ? make_float2(p3.y, -p3.x) : make_float2(-p3.y, p3.x);
    float2 jq3 = (DIR > 0) ? make_float2(q3.y, -q3.x) : make_float2(-q3.y, q3.x);
    a[0] = make_float2(p0.x + p2.x, p0.y + p2.y);
    a[4] = make_float2(p0.x - p2.x, p0.y - p2.y);
    a[2] = make_float2(p1.x + jp3.x, p1.y + jp3.y);
    a[6] = make_float2(p1.x - jp3.x, p1.y - jp3.y);
    a[1] = make_float2(q0.x + q2.x, q0.y + q2.y);
    a[5] = make_float2(q0.x - q2.x, q0.y - q2.y);
    a[3] = make_float2(q1.x + jq3.x, q1.y + jq3.y);
    a[7] = make_float2(q1.x - jq3.x, q1.y - jq3.y);
}

// twiddle via single load + power chain (log depth): w^k, k=1..7
template<int DIR, int TSH>
__device__ __forceinline__ void stage_tw_store(float2* dst, float2 a[8], int i) {
    const int s = 1 << TSH;
    int ps = (i >> TSH) << TSH;
    if (TSH < 9) {
        float2 w1 = g_tw[ps];
        if (DIR < 0) w1.y = -w1.y;
        float2 w2 = cmulf(w1, w1);
        float2 w3 = cmulf(w2, w1);
        float2 w4 = cmulf(w2, w2);
        float2 w5 = cmulf(w3, w2);
        float2 w6 = cmulf(w3, w3);
        float2 w7 = cmulf(w4, w3);
        a[1] = cmulf(a[1], w1);
        a[2] = cmulf(a[2], w2);
        a[3] = cmulf(a[3], w3);
        a[4] = cmulf(a[4], w4);
        a[5] = cmulf(a[5], w5);
        a[6] = cmulf(a[6], w6);
        a[7] = cmulf(a[7], w7);
    }
    int base = (i & (s - 1)) + (ps << 3);
    #pragma unroll
    for (int k = 0; k < 8; ++k) dst[SWZ(base + (k << TSH))] = a[k];
}

__global__ __launch_bounds__(512, 2) void fft_conv8_kernel() {
    extern __shared__ float2 sm[];
    float2* S0 = sm;
    float2* S1 = sm + NFFT;
    int d  = blockIdx.x & (DDIM - 1);
    int i  = threadIdx.x;
    float2* sig = g_zT + (size_t)blockIdx.x * NFFT;
    float2 a[8];

    // ---- forward ----
    #pragma unroll
    for (int j = 0; j < 8; ++j) a[j] = sig[i + j * 512];
    bfly8<1>(a); stage_tw_store<1, 0>(S0, a, i);
    __syncthreads();
    #pragma unroll
    for (int j = 0; j < 8; ++j) a[j] = S0[SWZ(i + j * 512)];
    bfly8<1>(a); stage_tw_store<1, 3>(S1, a, i);
    __syncthreads();
    #pragma unroll
    for (int j = 0; j < 8; ++j) a[j] = S1[SWZ(i + j * 512)];
    bfly8<1>(a); stage_tw_store<1, 6>(S0, a, i);
    __syncthreads();
    #pragma unroll
    for (int j = 0; j < 8; ++j) a[j] = S0[SWZ(i + j * 512)];
    bfly8<1>(a);
    // F3 (TSH=9): no twiddles; a[j] IS natural-order bin (i + j*512).
    {
        const float2* kf = g_Kf + (d << 12);
        #pragma unroll
        for (int j = 0; j < 8; ++j) a[j] = cmulf(a[j], __ldg(&kf[i + j * 512]));
    }
    // ---- inverse ----
    bfly8<-1>(a); stage_tw_store<-1, 0>(S1, a, i);
    __syncthreads();
    #pragma unroll
    for (int j = 0; j < 8; ++j) a[j] = S1[SWZ(i + j * 512)];
    bfly8<-1>(a); stage_tw_store<-1, 3>(S0, a, i);
    __syncthreads();
    #pragma unroll
    for (int j = 0; j < 8; ++j) a[j] = S0[SWZ(i + j * 512)];
    bfly8<-1>(a); stage_tw_store<-1, 6>(S1, a, i);
    __syncthreads();
    #pragma unroll
    for (int j = 0; j < 8; ++j) a[j] = S1[SWZ(i + j * 512)];
    bfly8<-1>(a);
    #pragma unroll
    for (int k = 0; k < 8; ++k) sig[i + k * 512] = a[k];
}

// ---------------- untranspose + split Re/Im (32d x 64l tiles, MLP=4) --------
__global__ __launch_bounds__(256) void t2_kernel(float* __restrict__ y) {
    __shared__ float2 tile[32][65];
    int b4 = blockIdx.z;
    int d0 = blockIdx.x << 5;
    int l0 = blockIdx.y << 6;
    int tid = threadIdx.x;
    const float4* zT4 = (const float4*)g_zT;
    #pragma unroll
    for (int u = 0; u < 4; ++u) {
        int m = tid + (u << 8);
        int dd = m >> 5, lp = m & 31;
        float4 v = zT4[(((b4 * DDIM) + d0 + dd) * NFFT + l0 + 2 * lp) >> 1];
        tile[dd][2 * lp]     = make_float2(v.x, v.y);
        tile[dd][2 * lp + 1] = make_float2(v.z, v.w);
    }
    __syncthreads();
    float4* y4 = (float4*)y;
    #pragma unroll
    for (int u = 0; u < 4; ++u) {
        int m = tid + (u << 8);
        int k = m & 7, l = (m >> 3) & 63;
        int plane = m >> 9;                        // u<2 -> 0 (Re), u>=2 -> 1 (Im)
        float2 t0 = tile[4 * k + 0][l];
        float2 t1 = tile[4 * k + 1][l];
        float2 t2 = tile[4 * k + 2][l];
        float2 t3 = tile[4 * k + 3][l];
        int row = ((b4 + plane * 4) * NFFT + l0 + l) * (DDIM / 4) + (d0 >> 2) + k;
        y4[row] = plane ? make_float4(t0.y, t1.y, t2.y, t3.y)
                        : make_float4(t0.x, t1.x, t2.x, t3.x);
    }
}

// ---------------- launcher ----------------
extern "C" void kernel_launch(void* const* d_in, const int* in_sizes, int n_in,
                              void* d_out, int out_size) {
    const float*  x   = (const float*)d_in[0];
    const float2* lam = (const float2*)d_in[1];
    const float2* P   = (const float2*)d_in[2];
    const float2* B   = (const float2*)d_in[3];
    const float2* C   = (const float2*)d_in[4];
    const float*  Dp  = (const float*)d_in[5];
    const float*  ld  = (const float*)d_in[6];
    float* y = (float*)d_out;

    cudaFuncSetAttribute(fft_conv8_kernel,
                         cudaFuncAttributeMaxDynamicSharedMemorySize,
                         2 * NFFT * sizeof(float2));

    kf_t1_kernel<<<2048 + 4096 + 16, 256>>>(x, lam, P, B, C, ld, Dp);
    fft_conv8_kernel<<<NB4 * DDIM, 512, 2 * NFFT * sizeof(float2)>>>();
    t2_kernel<<<dim3(DDIM / 32, NFFT / 64, NB4), dim3(256)>>>(y);
}

// round 8
// speedup vs baseline: 1.2584x; 1.0215x over previous
#include <cuda_runtime.h>
#include <math.h>

#define NFFT 4096
#define DDIM 256
#define HDIM 64
#define NB4  4   // BATCH/2 packed complex batches

typedef unsigned long long u64;

// ---------------- device scratch ----------------
__device__ float2 g_tw[NFFT];                 // e^{-2*pi*i*k/N}
__device__ float2 g_Kf[DDIM * NFFT];          // Hermitian (kernel+D) spectrum / N
__device__ float2 g_zT[NB4 * DDIM * NFFT];    // packed transposed signals

// ---------------- f32x2 packed helpers ----------------
__device__ __forceinline__ u64 pk2(float a, float b) {
    u64 r; asm("mov.b64 %0,{%1,%2};" : "=l"(r) : "f"(a), "f"(b)); return r;
}
__device__ __forceinline__ void upk2(u64 v, float& a, float& b) {
    asm("mov.b64 {%0,%1},%2;" : "=f"(a), "=f"(b) : "l"(v));
}
__device__ __forceinline__ u64 fma2(u64 a, u64 b, u64 c) {
    u64 d; asm("fma.rn.f32x2 %0,%1,%2,%3;" : "=l"(d) : "l"(a), "l"(b), "l"(c)); return d;
}
__device__ __forceinline__ u64 add2(u64 a, u64 b) {
    u64 d; asm("add.rn.f32x2 %0,%1,%2;" : "=l"(d) : "l"(a), "l"(b)); return d;
}
__device__ __forceinline__ u64 mul2(u64 a, u64 b) {
    u64 d; asm("mul.rn.f32x2 %0,%1,%2;" : "=l"(d) : "l"(a), "l"(b)); return d;
}

// =====================================================================
// Fused kernel A: blocks [0, 2048)    -> Cauchy/Woodbury spectrum (+ D/N fold)
//                 blocks [2048, 4096) -> transpose (B,L,D)->(B4,D,L), MLP=4
//                 blocks [4096, 4112) -> twiddle table (consumed by NEXT launch)
// =====================================================================
__global__ __launch_bounds__(256) void kf_t1_kernel(
    const float* __restrict__ x,
    const float2* __restrict__ lam, const float2* __restrict__ P,
    const float2* __restrict__ B,   const float2* __restrict__ C,
    const float* __restrict__ log_delta, const float* __restrict__ Dp)
{
    __shared__ float2 slam[HDIM];
    __shared__ float4 sNW[HDIM];              // (-lx, -ly, w11, -w11)
    __shared__ float4 sA[HDIM];               // (w00x, -w00x, w00y, w00y)
    __shared__ float4 sB[HDIM];               // (w01x, -w01x, w01y, w01y)
    __shared__ float4 sC[HDIM];               // (w10x, -w10x, w10y, w10y)
    __shared__ float2 tile[64][33];

    int tid = threadIdx.x;

    if (blockIdx.x < 2048) {
        // -------- kf path: d in [0,256), part in [0,8) --------
        int d    = blockIdx.x >> 3;
        int part = blockIdx.x & 7;

        if (tid < HDIM) slam[tid] = lam[tid];
        __syncthreads();
        if (tid < HDIM) {
            float2 L = slam[tid];
            float best = 3.4e38f; int bi = tid;
            #pragma unroll 8
            for (int j = 0; j < HDIM; ++j) {
                float2 M = slam[j];
                float dx = M.x - L.x, dy = M.y + L.y;   // |lam_j - conj(lam_h)|^2
                float e = dx * dx + dy * dy;
                if (e < best) { best = e; bi = j; }
            }
            float2 c  = C[(d << 6) + tid];
            float2 c2 = C[(d << 6) | bi];
            float chx = 0.5f * (c.x + c2.x);
            float chy = 0.5f * (c.y - c2.y);           // Chat = (C_h + conj(C_hbar))/2
            float2 b = B[(d << 6) + tid];
            float2 p = P[tid];
            float w00x = chx * b.x - chy * b.y, w00y = chx * b.y + chy * b.x;
            float w01x = chx * p.x - chy * p.y, w01y = chx * p.y + chy * p.x;
            float w10x = p.x * b.x + p.y * b.y, w10y = p.x * b.y - p.y * b.x;
            float w11  = p.x * p.x + p.y * p.y;
            sNW[tid] = make_float4(-L.x, -L.y, w11, -w11);
            sA[tid]  = make_float4(w00x, -w00x, w00y, w00y);
            sB[tid]  = make_float4(w01x, -w01x, w01y, w01y);
            sC[tid]  = make_float4(w10x, -w10x, w10y, w10y);
        }
        __syncthreads();

        float delta = __expf(log_delta[d]);
        const float sc = 1.0f / (float)NFFT;       // fold 1/N of inverse FFT
        float dsc = Dp[d] * sc;                    // D*x folded: Kf += D/N at every bin

        // Nyquist bin (z = -1): at = 0.5*delta*sum_h Re(w00)
        if (part == 0 && tid == 0) {
            float s = 0.0f;
            #pragma unroll
            for (int h = 0; h < HDIM; ++h) s += sA[h].x;
            g_Kf[(d << 12) + 2048] = make_float2(0.5f * delta * s * sc + dsc, 0.0f);
        }

        int l = part * 256 + tid;                  // [0, 2048)
        // z = e^{+2*pi*i*l/N}; l/2048 is dyadic-exact -> sincospif exact-arg
        float zr, zi;
        sincospif((float)l * (1.0f / 2048.0f), &zi, &zr);
        float ux = 1.0f + zr, uy = zi;             // u = 1+z (never 0 for l<2048)
        float vx = 2.0f - 2.0f * zr, vy = -2.0f * zi;
        float udx = ux * delta, udy = uy * delta;
        float di = __fdividef(1.0f, udx * udx + udy * udy);
        float gx = (vx * udx + vy * udy) * di;     // g = v/(u*delta)
        float gy = (vy * udx - vx * udy) * di;
        u64 g2 = pk2(gx, gy);

        // Inner loop: q = g - lam; t = q/|q|^2 = (rr, -ri) where r = conj(q)/|q|^2.
        // Complex accumulation with sign-adjusted weights:
        //   s += (wx,-wx).*t + (wy,wy).*swap(t)  == (wx*rr - wy*ri, wx*ri + wy*rr)
        //   s11 (real w11): (w11,-w11).*t == (w11*rr, w11*ri)
        u64 s00 = 0ull, s01 = 0ull, s10 = 0ull, s11 = 0ull;
        const ulonglong2* pNW = (const ulonglong2*)sNW;
        const ulonglong2* pA  = (const ulonglong2*)sA;
        const ulonglong2* pB  = (const ulonglong2*)sB;
        const ulonglong2* pC  = (const ulonglong2*)sC;
        #pragma unroll 16
        for (int h = 0; h < HDIM; ++h) {
            ulonglong2 NW = pNW[h];
            u64 q = add2(g2, NW.x);
            float qx, qy; upk2(q, qx, qy);
            float im = __fdividef(1.0f, fmaf(qx, qx, qy * qy));
            u64 t = mul2(q, pk2(im, im));
            float tx, ty; upk2(t, tx, ty);
            u64 tsw = pk2(ty, tx);
            s11 = fma2(NW.y, t, s11);
            ulonglong2 A = pA[h];  s00 = fma2(A.x, t, s00); s00 = fma2(A.y, tsw, s00);
            ulonglong2 Bv = pB[h]; s01 = fma2(Bv.x, t, s01); s01 = fma2(Bv.y, tsw, s01);
            ulonglong2 Cv = pC[h]; s10 = fma2(Cv.x, t, s10); s10 = fma2(Cv.y, tsw, s10);
        }
        float s00x, s00y, s01x, s01y, s10x, s10y, s11x, s11y;
        upk2(s00, s00x, s00y); upk2(s01, s01x, s01y);
        upk2(s10, s10x, s10y); upk2(s11, s11x, s11y);

        float nx  = s01x * s10x - s01y * s10y;
        float ny  = s01x * s10y + s01y * s10x;
        float dnx = 1.0f + s11x, dny = s11y;
        float ddi = __fdividef(1.0f, dnx * dnx + dny * dny);
        float cx  = (nx * dnx + ny * dny) * ddi;
        float cy  = (ny * dnx - nx * dny) * ddi;
        float k0x = s00x - cx, k0y = s00y - cy;
        float ui  = __fdividef(2.0f, ux * ux + uy * uy);
        float ax  = (k0x * ux + k0y * uy) * ui;
        float ay  = (k0y * ux - k0x * uy) * ui;
        ax = ax * sc + dsc; ay *= sc;
        if (l == 0) ay = 0.0f;
        g_Kf[(d << 12) + l] = make_float2(ax, ay);
        if (l > 0)
            g_Kf[(d << 12) + (NFFT - l)] = make_float2(ax, -ay);
    } else if (blockIdx.x < 4096) {
        // -------- t1 path: 32d x 64l tiles, MLP=4 --------
        int m  = blockIdx.x - 2048;                // [0, 2048)
        int b4 = m >> 9;
        int lblk = (m >> 3) & 63;
        int dblk = m & 7;
        int d0 = dblk << 5, l0 = lblk << 6;
        const float4* x4 = (const float4*)x;
        float4 A[2], Bv[2];
        #pragma unroll
        for (int u = 0; u < 2; ++u) {
            int mm = tid + (u << 8);               // [0, 512)
            int l = mm >> 3, d4 = mm & 7;
            int base0 = ((b4 * NFFT) + l0 + l) * (DDIM / 4) + (d0 >> 2) + d4;
            A[u]  = x4[base0];
            Bv[u] = x4[base0 + 4 * NFFT * (DDIM / 4)];
        }
        #pragma unroll
        for (int u = 0; u < 2; ++u) {
            int mm = tid + (u << 8);
            int l = mm >> 3, d4 = mm & 7;
            tile[l][4 * d4 + 0] = make_float2(A[u].x, Bv[u].x);
            tile[l][4 * d4 + 1] = make_float2(A[u].y, Bv[u].y);
            tile[l][4 * d4 + 2] = make_float2(A[u].z, Bv[u].z);
            tile[l][4 * d4 + 3] = make_float2(A[u].w, Bv[u].w);
        }
        __syncthreads();
        float4* zT4 = (float4*)g_zT;
        #pragma unroll
        for (int u = 0; u < 4; ++u) {
            int mm = tid + (u << 8);               // [0, 1024)
            int dd = mm >> 5, lp = mm & 31;
            float2 t0 = tile[2 * lp][dd];
            float2 t1 = tile[2 * lp + 1][dd];
            zT4[(((b4 * DDIM) + d0 + dd) * NFFT + l0 + 2 * lp) >> 1]
                = make_float4(t0.x, t0.y, t1.x, t1.y);
        }
    } else {
        // -------- twiddle table (used by the NEXT launch only) --------
        int k = (blockIdx.x - 4096) * 256 + tid;
        double ang = -6.283185307179586476925286766559 * (double)k / (double)NFFT;
        g_tw[k] = make_float2((float)cos(ang), (float)sin(ang));
    }
}

// ---------------- radix-8 Stockham FFT helpers ----------------
__device__ __forceinline__ float2 cmulf(float2 a, float2 b) {
    return make_float2(a.x * b.x - a.y * b.y, a.x * b.y + a.y * b.x);
}
#define SWZ(m) ((m) ^ (((m) >> 4) & 7))

template<int DIR>
__device__ __forceinline__ void bfly8(float2 a[8]) {
    const float S2 = 0.70710678118654752440f;
    float2 b0, b1, b2, b3, c0, c1, c2, c3;
    b0.x=a[0].x+a[4].x; b0.y=a[0].y+a[4].y;  c0.x=a[0].x-a[4].x; c0.y=a[0].y-a[4].y;
    b1.x=a[1].x+a[5].x; b1.y=a[1].y+a[5].y;  c1.x=a[1].x-a[5].x; c1.y=a[1].y-a[5].y;
    b2.x=a[2].x+a[6].x; b2.y=a[2].y+a[6].y;  c2.x=a[2].x-a[6].x; c2.y=a[2].y-a[6].y;
    b3.x=a[3].x+a[7].x; b3.y=a[3].y+a[7].y;  c3.x=a[3].x-a[7].x; c3.y=a[3].y-a[7].y;
    float2 tc1, tc2, tc3;
    if (DIR > 0) {
        tc1 = make_float2(S2 * (c1.x + c1.y),  S2 * (c1.y - c1.x));
        tc2 = make_float2(c2.y, -c2.x);
        tc3 = make_float2(S2 * (c3.y - c3.x), -S2 * (c3.x + c3.y));
    } else {
        tc1 = make_float2(S2 * (c1.x - c1.y),  S2 * (c1.y + c1.x));
        tc2 = make_float2(-c2.y, c2.x);
        tc3 = make_float2(-S2 * (c3.x + c3.y), S2 * (c3.x - c3.y));
    }
    float2 p0 = make_float2(b0.x + b2.x, b0.y + b2.y);
    float2 p1 = make_float2(b0.x - b2.x, b0.y - b2.y);
    float2 p2 = make_float2(b1.x + b3.x, b1.y + b3.y);
    float2 p3 = make_float2(b1.x - b3.x, b1.y - b3.y);
    float2 q0 = make_float2(c0.x + tc2.x, c0.y + tc2.y);
    float2 q1 = make_float2(c0.x - tc2.x, c0.y - tc2.y);
    float2 q2 = make_float2(tc1.x + tc3.x, tc1.y + tc3.y);
    float2 q3 = make_float2(tc1.x - tc3.x, tc1.y - tc3.y);
    float2 jp3 = (DIR > 0) ? make_float2(p3.y, -p3.x) : make_float2(-p3.y, p3.x);
    float2 jq3 = (DIR > 0) ? make_float2(q3.y, -q3.x) : make_float2(-q3.y, q3.x);
    a[0] = make_float2(p0.x + p2.x, p0.y + p2.y);
    a[4] = make_float2(p0.x - p2.x, p0.y - p2.y);
    a[2] = make_float2(p1.x + jp3.x, p1.y + jp3.y);
    a[6] = make_float2(p1.x - jp3.x, p1.y - jp3.y);
    a[1] = make_float2(q0.x + q2.x, q0.y + q2.y);
    a[5] = make_float2(q0.x - q2.x, q0.y - q2.y);
    a[3] = make_float2(q1.x + jq3.x, q1.y + jq3.y);
    a[7] = make_float2(q1.x - jq3.x, q1.y - jq3.y);
}

// twiddle via single load + power chain (log depth): w^k, k=1..7
template<int DIR, int TSH>
__device__ __forceinline__ void stage_tw_store(float2* dst, float2 a[8], int i) {
    const int s = 1 << TSH;
    int ps = (i >> TSH) << TSH;
    if (TSH < 9) {
        float2 w1 = g_tw[ps];
        if (DIR < 0) w1.y = -w1.y;
        float2 w2 = cmulf(w1, w1);
        float2 w3 = cmulf(w2, w1);
        float2 w4 = cmulf(w2, w2);
        float2 w5 = cmulf(w3, w2);
        float2 w6 = cmulf(w3, w3);
        float2 w7 = cmulf(w4, w3);
        a[1] = cmulf(a[1], w1);
        a[2] = cmulf(a[2], w2);
        a[3] = cmulf(a[3], w3);
        a[4] = cmulf(a[4], w4);
        a[5] = cmulf(a[5], w5);
        a[6] = cmulf(a[6], w6);
        a[7] = cmulf(a[7], w7);
    }
    int base = (i & (s - 1)) + (ps << 3);
    #pragma unroll
    for (int k = 0; k < 8; ++k) dst[SWZ(base + (k << TSH))] = a[k];
}

__global__ __launch_bounds__(512, 2) void fft_conv8_kernel() {
    extern __shared__ float2 sm[];
    float2* S0 = sm;
    float2* S1 = sm + NFFT;
    int d  = blockIdx.x & (DDIM - 1);
    int i  = threadIdx.x;
    float2* sig = g_zT + (size_t)blockIdx.x * NFFT;
    float2 a[8];

    // ---- forward ----
    #pragma unroll
    for (int j = 0; j < 8; ++j) a[j] = sig[i + j * 512];
    bfly8<1>(a); stage_tw_store<1, 0>(S0, a, i);
    __syncthreads();
    #pragma unroll
    for (int j = 0; j < 8; ++j) a[j] = S0[SWZ(i + j * 512)];
    bfly8<1>(a); stage_tw_store<1, 3>(S1, a, i);
    __syncthreads();
    #pragma unroll
    for (int j = 0; j < 8; ++j) a[j] = S1[SWZ(i + j * 512)];
    bfly8<1>(a); stage_tw_store<1, 6>(S0, a, i);
    __syncthreads();
    #pragma unroll
    for (int j = 0; j < 8; ++j) a[j] = S0[SWZ(i + j * 512)];
    bfly8<1>(a);
    // F3 (TSH=9): no twiddles; a[j] IS natural-order bin (i + j*512).
    {
        const float2* kf = g_Kf + (d << 12);
        #pragma unroll
        for (int j = 0; j < 8; ++j) a[j] = cmulf(a[j], __ldg(&kf[i + j * 512]));
    }
    // ---- inverse ----
    bfly8<-1>(a); stage_tw_store<-1, 0>(S1, a, i);
    __syncthreads();
    #pragma unroll
    for (int j = 0; j < 8; ++j) a[j] = S1[SWZ(i + j * 512)];
    bfly8<-1>(a); stage_tw_store<-1, 3>(S0, a, i);
    __syncthreads();
    #pragma unroll
    for (int j = 0; j < 8; ++j) a[j] = S0[SWZ(i + j * 512)];
    bfly8<-1>(a); stage_tw_store<-1, 6>(S1, a, i);
    __syncthreads();
    #pragma unroll
    for (int j = 0; j < 8; ++j) a[j] = S1[SWZ(i + j * 512)];
    bfly8<-1>(a);
    #pragma unroll
    for (int k = 0; k < 8; ++k) sig[i + k * 512] = a[k];
}

// ---------------- untranspose + split Re/Im (32d x 64l tiles, MLP=4) --------
__global__ __launch_bounds__(256) void t2_kernel(float* __restrict__ y) {
    __shared__ float2 tile[32][65];
    int b4 = blockIdx.z;
    int d0 = blockIdx.x << 5;
    int l0 = blockIdx.y << 6;
    int tid = threadIdx.x;
    const float4* zT4 = (const float4*)g_zT;
    #pragma unroll
    for (int u = 0; u < 4; ++u) {
        int m = tid + (u << 8);
        int dd = m >> 5, lp = m & 31;
        float4 v = zT4[(((b4 * DDIM) + d0 + dd) * NFFT + l0 + 2 * lp) >> 1];
        tile[dd][2 * lp]     = make_float2(v.x, v.y);
        tile[dd][2 * lp + 1] = make_float2(v.z, v.w);
    }
    __syncthreads();
    float4* y4 = (float4*)y;
    #pragma unroll
    for (int u = 0; u < 4; ++u) {
        int m = tid + (u << 8);
        int k = m & 7, l = (m >> 3) & 63;
        int plane = m >> 9;                        // u<2 -> 0 (Re), u>=2 -> 1 (Im)
        float2 t0 = tile[4 * k + 0][l];
        float2 t1 = tile[4 * k + 1][l];
        float2 t2 = tile[4 * k + 2][l];
        float2 t3 = tile[4 * k + 3][l];
        int row = ((b4 + plane * 4) * NFFT + l0 + l) * (DDIM / 4) + (d0 >> 2) + k;
        y4[row] = plane ? make_float4(t0.y, t1.y, t2.y, t3.y)
                        : make_float4(t0.x, t1.x, t2.x, t3.x);
    }
}

// ---------------- launcher ----------------
extern "C" void kernel_launch(void* const* d_in, const int* in_sizes, int n_in,
                              void* d_out, int out_size) {
    const float*  x   = (const float*)d_in[0];
    const float2* lam = (const float2*)d_in[1];
    const float2* P   = (const float2*)d_in[2];
    const float2* B   = (const float2*)d_in[3];
    const float2* C   = (const float2*)d_in[4];
    const float*  Dp  = (const float*)d_in[5];
    const float*  ld  = (const float*)d_in[6];
    float* y = (float*)d_out;

    cudaFuncSetAttribute(fft_conv8_kernel,
                         cudaFuncAttributeMaxDynamicSharedMemorySize,
                         2 * NFFT * sizeof(float2));

    kf_t1_kernel<<<2048 + 2048 + 16, 256>>>(x, lam, P, B, C, ld, Dp);
    fft_conv8_kernel<<<NB4 * DDIM, 512, 2 * NFFT * sizeof(float2)>>>();
    t2_kernel<<<dim3(DDIM / 32, NFFT / 64, NB4), dim3(256)>>>(y);
}

// round 9
// speedup vs baseline: 1.4364x; 1.1414x over previous
#include <cuda_runtime.h>
#include <math.h>

#define NFFT 4096
#define DDIM 256
#define HDIM 64
#define NB4  4   // BATCH/2 packed complex batches

typedef unsigned long long u64;

// ---------------- device scratch ----------------
__device__ float2 g_tw[NFFT];                 // e^{-2*pi*i*k/N}
__device__ float2 g_Kf[DDIM * NFFT];          // Hermitian (kernel+D) spectrum / N
__device__ float2 g_zT[NB4 * DDIM * NFFT];    // packed transposed signals

// ---------------- f32x2 packed helpers ----------------
__device__ __forceinline__ u64 pk2(float a, float b) {
    u64 r; asm("mov.b64 %0,{%1,%2};" : "=l"(r) : "f"(a), "f"(b)); return r;
}
__device__ __forceinline__ void upk2(u64 v, float& a, float& b) {
    asm("mov.b64 {%0,%1},%2;" : "=f"(a), "=f"(b) : "l"(v));
}
__device__ __forceinline__ u64 fma2(u64 a, u64 b, u64 c) {
    u64 d; asm("fma.rn.f32x2 %0,%1,%2,%3;" : "=l"(d) : "l"(a), "l"(b), "l"(c)); return d;
}

// =====================================================================
// Fused kernel A: blocks [0, 2048)    -> pair-reduced Cauchy spectrum (+ D/N)
//                 blocks [2048, 4096) -> transpose (B,L,D)->(B4,D,L), MLP=4
//                 blocks [4096, 4112) -> twiddle table (consumed by NEXT launch)
//
// Pair reduction: g = iG (purely imaginary on |z|=1). For a pole pair with
// conj structure:  v1/(iG-u1) + v2/(iG-u2) = (e0 + i e1 G)/((m - G^2) - i n G)
// with m=Re(u1u2), n=Re(u1+u2), e1=Re(v1+v2), e0=-Re(v1 u2 + v2 u1), all real.
// 64 poles -> 32 slots; denominator/reciprocal shared by all 4 Woodbury sums.
// =====================================================================
__global__ __launch_bounds__(256) void kf_t1_kernel(
    const float* __restrict__ x,
    const float2* __restrict__ lam, const float2* __restrict__ P,
    const float2* __restrict__ B,   const float2* __restrict__ C,
    const float* __restrict__ log_delta, const float* __restrict__ Dp)
{
    __shared__ float2 slam[HDIM];
    __shared__ float4 tW0[HDIM];              // (w00x, w00y, w01x, w01y)
    __shared__ float4 tW1[HDIM];              // (w10x, w10y, w11, 0)
    __shared__ int    sbi[HDIM];
    __shared__ unsigned sLm[2], sRm[2];
    __shared__ int    pA[32], pB[32], realIdx[HDIM];
    __shared__ float2 sMN[32];                // (m, n)
    __shared__ float4 sE0a[32];               // (e0_00,e0_00,e0_01,e0_01)
    __shared__ float4 sE1a[32];               // (e1_00,e1_00,e1_01,e1_01)
    __shared__ float4 sE0b[32];               // (e0_10,e0_10,e0_11,e0_11)
    __shared__ float4 sE1b[32];               // (e1_10,e1_10,e1_11,e1_11)
    __shared__ float2 tile[64][33];

    int tid = threadIdx.x;

    if (blockIdx.x < 2048) {
        // -------- kf path: d in [0,256), part in [0,8) --------
        int d    = blockIdx.x >> 3;
        int part = blockIdx.x & 7;

        if (tid < HDIM) slam[tid] = lam[tid];
        __syncthreads();
        if (tid < HDIM) {
            float2 L = slam[tid];
            float best = 3.4e38f; int bi = tid;
            #pragma unroll 8
            for (int j = 0; j < HDIM; ++j) {
                float2 M = slam[j];
                float dx = M.x - L.x, dy = M.y + L.y;   // |lam_j - conj(lam_h)|^2
                float e = dx * dx + dy * dy;
                if (e < best) { best = e; bi = j; }
            }
            sbi[tid] = bi;
            float2 c  = C[(d << 6) + tid];
            float2 c2 = C[(d << 6) | bi];
            float chx = 0.5f * (c.x + c2.x);
            float chy = 0.5f * (c.y - c2.y);           // Chat = (C_h + conj(C_hbar))/2
            float2 b = B[(d << 6) + tid];
            float2 p = P[tid];
            float w00x = chx * b.x - chy * b.y, w00y = chx * b.y + chy * b.x;
            float w01x = chx * p.x - chy * p.y, w01y = chx * p.y + chy * p.x;
            float w10x = p.x * b.x + p.y * b.y, w10y = p.x * b.y - p.y * b.x;
            float w11  = p.x * p.x + p.y * p.y;
            tW0[tid] = make_float4(w00x, w00y, w01x, w01y);
            tW1[tid] = make_float4(w10x, w10y, w11, 0.0f);
        }
        __syncthreads();
        // ballots: warps 0,1 fully cover tid<64
        if (tid < HDIM) {
            int bi = sbi[tid];
            unsigned lm = __ballot_sync(0xffffffffu, bi > tid);
            unsigned rm = __ballot_sync(0xffffffffu, bi == tid);
            if ((tid & 31) == 0) { sLm[tid >> 5] = lm; sRm[tid >> 5] = rm; }
        }
        __syncthreads();
        if (tid < HDIM) {
            int lane = tid & 31, w = tid >> 5;
            int bi = sbi[tid];
            unsigned below = (1u << lane) - 1u;
            if (bi > tid) {                    // conj-pair lead
                int slot = __popc(sLm[w] & below) + (w ? __popc(sLm[0]) : 0);
                pA[slot] = tid; pB[slot] = bi;
            } else if (bi == tid) {            // real pole: record rank
                int r = __popc(sRm[w] & below) + (w ? __popc(sRm[0]) : 0);
                realIdx[r] = tid;
            }
        }
        __syncthreads();
        if (tid < HDIM) {
            int bi = sbi[tid];
            if (bi == tid) {
                int lane = tid & 31, w = tid >> 5;
                int r = __popc(sRm[w] & ((1u << lane) - 1u)) + (w ? __popc(sRm[0]) : 0);
                if (!(r & 1)) {                // even-rank real creates the slot
                    int nLead = __popc(sLm[0]) + __popc(sLm[1]);
                    int nReal = __popc(sRm[0]) + __popc(sRm[1]);
                    int slot = nLead + (r >> 1);
                    pA[slot] = tid;
                    pB[slot] = (r + 1 < nReal) ? realIdx[r + 1] : -1;
                }
            }
        }
        __syncthreads();
        // slot parameters
        if (tid < 32) {
            int h1 = pA[tid], h2r = pB[tid];
            int h2 = (h2r >= 0) ? h2r : h1;
            float zf = (h2r >= 0) ? 1.0f : 0.0f;
            float2 u1 = slam[h1], u2 = slam[h2];
            float m = u1.x * u2.x - u1.y * u2.y;
            float n = u1.x + u2.x;
            sMN[tid] = make_float2(m, n);
            float4 a1 = tW0[h1], a2 = tW0[h2];
            float4 b1 = tW1[h1], b2 = tW1[h2];
            float e1_00 = a1.x + zf * a2.x;
            float e0_00 = -(a1.x * u2.x - a1.y * u2.y + zf * (a2.x * u1.x - a2.y * u1.y));
            float e1_01 = a1.z + zf * a2.z;
            float e0_01 = -(a1.z * u2.x - a1.w * u2.y + zf * (a2.z * u1.x - a2.w * u1.y));
            float e1_10 = b1.x + zf * b2.x;
            float e0_10 = -(b1.x * u2.x - b1.y * u2.y + zf * (b2.x * u1.x - b2.y * u1.y));
            float e1_11 = b1.z + zf * b2.z;
            float e0_11 = -(b1.z * u2.x + zf * b2.z * u1.x);
            sE0a[tid] = make_float4(e0_00, e0_00, e0_01, e0_01);
            sE1a[tid] = make_float4(e1_00, e1_00, e1_01, e1_01);
            sE0b[tid] = make_float4(e0_10, e0_10, e0_11, e0_11);
            sE1b[tid] = make_float4(e1_10, e1_10, e1_11, e1_11);
        }
        __syncthreads();

        float delta = __expf(log_delta[d]);
        const float sc = 1.0f / (float)NFFT;       // fold 1/N of inverse FFT
        float dsc = Dp[d] * sc;                    // D*x folded: Kf += D/N at every bin

        // Nyquist bin (z = -1): at = 0.5*delta*sum_h Re(w00) = 0.5*delta*sum_s e1_00
        if (part == 0 && tid == 0) {
            float s = 0.0f;
            #pragma unroll
            for (int q = 0; q < 32; ++q) s += sE1a[q].x;
            g_Kf[(d << 12) + 2048] = make_float2(0.5f * delta * s * sc + dsc, 0.0f);
        }

        int l = part * 256 + tid;                  // [0, 2048)
        // half-angle: th = tan(pi*l/4096); g = iG, G = -(2/delta)*th
        float s_, c_;
        sincospif((float)l * (1.0f / 4096.0f), &s_, &c_);
        float th = __fdividef(s_, c_);
        float G  = th * __fdividef(-2.0f, delta);
        float Gsq = G * G;

        u64 s00 = 0ull, s01 = 0ull, s10 = 0ull, s11 = 0ull;
        const ulonglong2* pE0a = (const ulonglong2*)sE0a;
        const ulonglong2* pE1a = (const ulonglong2*)sE1a;
        const ulonglong2* pE0b = (const ulonglong2*)sE0b;
        const ulonglong2* pE1b = (const ulonglong2*)sE1b;
        #pragma unroll 8
        for (int s = 0; s < 32; ++s) {
            float2 mn = sMN[s];
            float dx  = mn.x - Gsq;
            float dyn = mn.y * G;                  // conj(D) = (dx, dyn)
            float den = fmaf(dx, dx, dyn * dyn);
            float im  = __fdividef(1.0f, den);
            float tx = dx * im, ty = dyn * im;     // t = 1/D
            u64 t  = pk2(tx, ty);
            float Gtx = G * tx, nGty = -G * ty;
            u64 tg = pk2(nGty, Gtx);               // i*G/D pattern
            ulonglong2 E0a = pE0a[s];
            ulonglong2 E1a = pE1a[s];
            s00 = fma2(E0a.x, t, s00); s00 = fma2(E1a.x, tg, s00);
            s01 = fma2(E0a.y, t, s01); s01 = fma2(E1a.y, tg, s01);
            ulonglong2 E0b = pE0b[s];
            ulonglong2 E1b = pE1b[s];
            s10 = fma2(E0b.x, t, s10); s10 = fma2(E1b.x, tg, s10);
            s11 = fma2(E0b.y, t, s11); s11 = fma2(E1b.y, tg, s11);
        }
        float s00x, s00y, s01x, s01y, s10x, s10y, s11x, s11y;
        upk2(s00, s00x, s00y); upk2(s01, s01x, s01y);
        upk2(s10, s10x, s10y); upk2(s11, s11x, s11y);

        float nx  = s01x * s10x - s01y * s10y;
        float ny  = s01x * s10y + s01y * s10x;
        float dnx = 1.0f + s11x, dny = s11y;
        float ddi = __fdividef(1.0f, dnx * dnx + dny * dny);
        float cx  = (nx * dnx + ny * dny) * ddi;
        float cy  = (ny * dnx - nx * dny) * ddi;
        float k0x = s00x - cx, k0y = s00y - cy;
        // 2/u = 1 - i*th
        float ax = k0x + th * k0y;
        float ay = k0y - th * k0x;
        ax = ax * sc + dsc; ay *= sc;
        if (l == 0) ay = 0.0f;
        g_Kf[(d << 12) + l] = make_float2(ax, ay);
        if (l > 0)
            g_Kf[(d << 12) + (NFFT - l)] = make_float2(ax, -ay);
    } else if (blockIdx.x < 4096) {
        // -------- t1 path: 32d x 64l tiles, MLP=4 --------
        int m  = blockIdx.x - 2048;                // [0, 2048)
        int b4 = m >> 9;
        int lblk = (m >> 3) & 63;
        int dblk = m & 7;
        int d0 = dblk << 5, l0 = lblk << 6;
        const float4* x4 = (const float4*)x;
        float4 A[2], Bv[2];
        #pragma unroll
        for (int u = 0; u < 2; ++u) {
            int mm = tid + (u << 8);               // [0, 512)
            int l = mm >> 3, d4 = mm & 7;
            int base0 = ((b4 * NFFT) + l0 + l) * (DDIM / 4) + (d0 >> 2) + d4;
            A[u]  = x4[base0];
            Bv[u] = x4[base0 + 4 * NFFT * (DDIM / 4)];
        }
        #pragma unroll
        for (int u = 0; u < 2; ++u) {
            int mm = tid + (u << 8);
            int l = mm >> 3, d4 = mm & 7;
            tile[l][4 * d4 + 0] = make_float2(A[u].x, Bv[u].x);
            tile[l][4 * d4 + 1] = make_float2(A[u].y, Bv[u].y);
            tile[l][4 * d4 + 2] = make_float2(A[u].z, Bv[u].z);
            tile[l][4 * d4 + 3] = make_float2(A[u].w, Bv[u].w);
        }
        __syncthreads();
        float4* zT4 = (float4*)g_zT;
        #pragma unroll
        for (int u = 0; u < 4; ++u) {
            int mm = tid + (u << 8);               // [0, 1024)
            int dd = mm >> 5, lp = mm & 31;
            float2 t0 = tile[2 * lp][dd];
            float2 t1 = tile[2 * lp + 1][dd];
            zT4[(((b4 * DDIM) + d0 + dd) * NFFT + l0 + 2 * lp) >> 1]
                = make_float4(t0.x, t0.y, t1.x, t1.y);
        }
    } else {
        // -------- twiddle table (used by the NEXT launch only) --------
        int k = (blockIdx.x - 4096) * 256 + tid;
        double ang = -6.283185307179586476925286766559 * (double)k / (double)NFFT;
        g_tw[k] = make_float2((float)cos(ang), (float)sin(ang));
    }
}

// ---------------- radix-8 Stockham FFT helpers ----------------
__device__ __forceinline__ float2 cmulf(float2 a, float2 b) {
    return make_float2(a.x * b.x - a.y * b.y, a.x * b.y + a.y * b.x);
}
#define SWZ(m) ((m) ^ (((m) >> 4) & 7))

template<int DIR>
__device__ __forceinline__ void bfly8(float2 a[8]) {
    const float S2 = 0.70710678118654752440f;
    float2 b0, b1, b2, b3, c0, c1, c2, c3;
    b0.x=a[0].x+a[4].x; b0.y=a[0].y+a[4].y;  c0.x=a[0].x-a[4].x; c0.y=a[0].y-a[4].y;
    b1.x=a[1].x+a[5].x; b1.y=a[1].y+a[5].y;  c1.x=a[1].x-a[5].x; c1.y=a[1].y-a[5].y;
    b2.x=a[2].x+a[6].x; b2.y=a[2].y+a[6].y;  c2.x=a[2].x-a[6].x; c2.y=a[2].y-a[6].y;
    b3.x=a[3].x+a[7].x; b3.y=a[3].y+a[7].y;  c3.x=a[3].x-a[7].x; c3.y=a[3].y-a[7].y;
    float2 tc1, tc2, tc3;
    if (DIR > 0) {
        tc1 = make_float2(S2 * (c1.x + c1.y),  S2 * (c1.y - c1.x));
        tc2 = make_float2(c2.y, -c2.x);
        tc3 = make_float2(S2 * (c3.y - c3.x), -S2 * (c3.x + c3.y));
    } else {
        tc1 = make_float2(S2 * (c1.x - c1.y),  S2 * (c1.y + c1.x));
        tc2 = make_float2(-c2.y, c2.x);
        tc3 = make_float2(-S2 * (c3.x + c3.y), S2 * (c3.x - c3.y));
    }
    float2 p0 = make_float2(b0.x + b2.x, b0.y + b2.y);
    float2 p1 = make_float2(b0.x - b2.x, b0.y - b2.y);
    float2 p2 = make_float2(b1.x + b3.x, b1.y + b3.y);
    float2 p3 = make_float2(b1.x - b3.x, b1.y - b3.y);
    float2 q0 = make_float2(c0.x + tc2.x, c0.y + tc2.y);
    float2 q1 = make_float2(c0.x - tc2.x, c0.y - tc2.y);
    float2 q2 = make_float2(tc1.x + tc3.x, tc1.y + tc3.y);
    float2 q3 = make_float2(tc1.x - tc3.x, tc1.y - tc3.y);
    float2 jp3 = (DIR > 0) ? make_float2(p3.y, -p3.x) : make_float2(-p3.y, p3.x);
    float2 jq3 = (DIR > 0) ? make_float2(q3.y, -q3.x) : make_float2(-q3.y, q3.x);
    a[0] = make_float2(p0.x + p2.x, p0.y + p2.y);
    a[4] = make_float2(p0.x - p2.x, p0.y - p2.y);
    a[2] = make_float2(p1.x + jp3.x, p1.y + jp3.y);
    a[6] = make_float2(p1.x - jp3.x, p1.y - jp3.y);
    a[1] = make_float2(q0.x + q2.x, q0.y + q2.y);
    a[5] = make_float2(q0.x - q2.x, q0.y - q2.y);
    a[3] = make_float2(q1.x + jq3.x, q1.y + jq3.y);
    a[7] = make_float2(q1.x - jq3.x, q1.y - jq3.y);
}

// twiddle via single load + power chain (log depth): w^k, k=1..7
template<int DIR, int TSH>
__device__ __forceinline__ void stage_tw_store(float2* dst, float2 a[8], int i) {
    const int s = 1 << TSH;
    int ps = (i >> TSH) << TSH;
    if (TSH < 9) {
        float2 w1 = g_tw[ps];
        if (DIR < 0) w1.y = -w1.y;
        float2 w2 = cmulf(w1, w1);
        float2 w3 = cmulf(w2, w1);
        float2 w4 = cmulf(w2, w2);
        float2 w5 = cmulf(w3, w2);
        float2 w6 = cmulf(w3, w3);
        float2 w7 = cmulf(w4, w3);
        a[1] = cmulf(a[1], w1);
        a[2] = cmulf(a[2], w2);
        a[3] = cmulf(a[3], w3);
        a[4] = cmulf(a[4], w4);
        a[5] = cmulf(a[5], w5);
        a[6] = cmulf(a[6], w6);
        a[7] = cmulf(a[7], w7);
    }
    int base = (i & (s - 1)) + (ps << 3);
    #pragma unroll
    for (int k = 0; k < 8; ++k) dst[SWZ(base + (k << TSH))] = a[k];
}

__global__ __launch_bounds__(512, 2) void fft_conv8_kernel() {
    extern __shared__ float2 sm[];
    float2* S0 = sm;
    float2* S1 = sm + NFFT;
    int d  = blockIdx.x & (DDIM - 1);
    int i  = threadIdx.x;
    float2* sig = g_zT + (size_t)blockIdx.x * NFFT;
    float2 a[8];

    // ---- forward ----
    #pragma unroll
    for (int j = 0; j < 8; ++j) a[j] = sig[i + j * 512];
    bfly8<1>(a); stage_tw_store<1, 0>(S0, a, i);
    __syncthreads();
    #pragma unroll
    for (int j = 0; j < 8; ++j) a[j] = S0[SWZ(i + j * 512)];
    bfly8<1>(a); stage_tw_store<1, 3>(S1, a, i);
    __syncthreads();
    #pragma unroll
    for (int j = 0; j < 8; ++j) a[j] = S1[SWZ(i + j * 512)];
    bfly8<1>(a); stage_tw_store<1, 6>(S0, a, i);
    __syncthreads();
    #pragma unroll
    for (int j = 0; j < 8; ++j) a[j] = S0[SWZ(i + j * 512)];
    bfly8<1>(a);
    // F3 (TSH=9): no twiddles; a[j] IS natural-order bin (i + j*512).
    {
        const float2* kf = g_Kf + (d << 12);
        #pragma unroll
        for (int j = 0; j < 8; ++j) a[j] = cmulf(a[j], __ldg(&kf[i + j * 512]));
    }
    // ---- inverse ----
    bfly8<-1>(a); stage_tw_store<-1, 0>(S1, a, i);
    __syncthreads();
    #pragma unroll
    for (int j = 0; j < 8; ++j) a[j] = S1[SWZ(i + j * 512)];
    bfly8<-1>(a); stage_tw_store<-1, 3>(S0, a, i);
    __syncthreads();
    #pragma unroll
    for (int j = 0; j < 8; ++j) a[j] = S0[SWZ(i + j * 512)];
    bfly8<-1>(a); stage_tw_store<-1, 6>(S1, a, i);
    __syncthreads();
    #pragma unroll
    for (int j = 0; j < 8; ++j) a[j] = S1[SWZ(i + j * 512)];
    bfly8<-1>(a);
    #pragma unroll
    for (int k = 0; k < 8; ++k) sig[i + k * 512] = a[k];
}

// ---------------- untranspose + split Re/Im (32d x 64l tiles, MLP=4) --------
__global__ __launch_bounds__(256) void t2_kernel(float* __restrict__ y) {
    __shared__ float2 tile[32][65];
    int b4 = blockIdx.z;
    int d0 = blockIdx.x << 5;
    int l0 = blockIdx.y << 6;
    int tid = threadIdx.x;
    const float4* zT4 = (const float4*)g_zT;
    #pragma unroll
    for (int u = 0; u < 4; ++u) {
        int m = tid + (u << 8);
        int dd = m >> 5, lp = m & 31;
        float4 v = zT4[(((b4 * DDIM) + d0 + dd) * NFFT + l0 + 2 * lp) >> 1];
        tile[dd][2 * lp]     = make_float2(v.x, v.y);
        tile[dd][2 * lp + 1] = make_float2(v.z, v.w);
    }
    __syncthreads();
    float4* y4 = (float4*)y;
    #pragma unroll
    for (int u = 0; u < 4; ++u) {
        int m = tid + (u << 8);
        int k = m & 7, l = (m >> 3) & 63;
        int plane = m >> 9;                        // u<2 -> 0 (Re), u>=2 -> 1 (Im)
        float2 t0 = tile[4 * k + 0][l];
        float2 t1 = tile[4 * k + 1][l];
        float2 t2 = tile[4 * k + 2][l];
        float2 t3 = tile[4 * k + 3][l];
        int row = ((b4 + plane * 4) * NFFT + l0 + l) * (DDIM / 4) + (d0 >> 2) + k;
        y4[row] = plane ? make_float4(t0.y, t1.y, t2.y, t3.y)
                        : make_float4(t0.x, t1.x, t2.x, t3.x);
    }
}

// ---------------- launcher ----------------
extern "C" void kernel_launch(void* const* d_in, const int* in_sizes, int n_in,
                              void* d_out, int out_size) {
    const float*  x   = (const float*)d_in[0];
    const float2* lam = (const float2*)d_in[1];
    const float2* P   = (const float2*)d_in[2];
    const float2* B   = (const float2*)d_in[3];
    const float2* C   = (const float2*)d_in[4];
    const float*  Dp  = (const float*)d_in[5];
    const float*  ld  = (const float*)d_in[6];
    float* y = (float*)d_out;

    cudaFuncSetAttribute(fft_conv8_kernel,
                         cudaFuncAttributeMaxDynamicSharedMemorySize,
                         2 * NFFT * sizeof(float2));

    kf_t1_kernel<<<2048 + 2048 + 16, 256>>>(x, lam, P, B, C, ld, Dp);
    fft_conv8_kernel<<<NB4 * DDIM, 512, 2 * NFFT * sizeof(float2)>>>();
    t2_kernel<<<dim3(DDIM / 32, NFFT / 64, NB4), dim3(256)>>>(y);
}

// round 10
// speedup vs baseline: 1.4451x; 1.0061x over previous
#include <cuda_runtime.h>
#include <math.h>

#define NFFT 4096
#define DDIM 256
#define HDIM 64
#define NB4  4   // BATCH/2 packed complex batches

typedef unsigned long long u64;

// ---------------- device scratch ----------------
__device__ float2 g_tw[NFFT];                 // e^{-2*pi*i*k/N}
__device__ float2 g_Kf[DDIM * NFFT];          // Hermitian (kernel+D) spectrum / N
__device__ float2 g_zT[NB4 * DDIM * NFFT];    // packed transposed signals

// ---------------- f32x2 packed helpers ----------------
__device__ __forceinline__ u64 pk2(float a, float b) {
    u64 r; asm("mov.b64 %0,{%1,%2};" : "=l"(r) : "f"(a), "f"(b)); return r;
}
__device__ __forceinline__ void upk2(u64 v, float& a, float& b) {
    asm("mov.b64 {%0,%1},%2;" : "=f"(a), "=f"(b) : "l"(v));
}
__device__ __forceinline__ u64 fma2(u64 a, u64 b, u64 c) {
    u64 d; asm("fma.rn.f32x2 %0,%1,%2,%3;" : "=l"(d) : "l"(a), "l"(b), "l"(c)); return d;
}

// =====================================================================
// Fused kernel A: blocks [0, 1024)    -> pair-reduced Cauchy spectrum (+ D/N)
//                                        2 points/thread, G factored out
//                 blocks [1024, 3072) -> transpose (B,L,D)->(B4,D,L), MLP=4
//                 blocks [3072, 3088) -> twiddle table (consumed by NEXT launch)
//
// Pair reduction: g = iG (purely imaginary on |z|=1). For a pole pair:
//   v1/(iG-u1) + v2/(iG-u2) = (e0 + i e1 G)/((m - G^2) - i n G)
// G-factoring: accumulate P = sum e0*t, Q = sum e1*t (t = 1/conj-normalized
// denominator); s = P + iG*Q formed once per point.
// =====================================================================
__global__ __launch_bounds__(256) void kf_t1_kernel(
    const float* __restrict__ x,
    const float2* __restrict__ lam, const float2* __restrict__ P,
    const float2* __restrict__ B,   const float2* __restrict__ C,
    const float* __restrict__ log_delta, const float* __restrict__ Dp)
{
    __shared__ float2 slam[HDIM];
    __shared__ float4 tW0[HDIM];              // (w00x, w00y, w01x, w01y)
    __shared__ float4 tW1[HDIM];              // (w10x, w10y, w11, 0)
    __shared__ int    sbi[HDIM];
    __shared__ unsigned sLm[2], sRm[2];
    __shared__ int    pA[32], pB[32], realIdx[HDIM];
    __shared__ float2 sMN[32];                // (m, n)
    __shared__ float4 sE0a[32];               // (e0_00,e0_00,e0_01,e0_01)
    __shared__ float4 sE1a[32];               // (e1_00,e1_00,e1_01,e1_01)
    __shared__ float4 sE0b[32];               // (e0_10,e0_10,e0_11,e0_11)
    __shared__ float4 sE1b[32];               // (e1_10,e1_10,e1_11,e1_11)
    __shared__ float2 tile[64][33];

    int tid = threadIdx.x;

    if (blockIdx.x < 1024) {
        // -------- kf path: d in [0,256), part in [0,4), 2 points/thread -----
        int d    = blockIdx.x >> 2;
        int part = blockIdx.x & 3;

        if (tid < HDIM) slam[tid] = lam[tid];
        __syncthreads();
        if (tid < HDIM) {
            float2 L = slam[tid];
            float best = 3.4e38f; int bi = tid;
            #pragma unroll 8
            for (int j = 0; j < HDIM; ++j) {
                float2 M = slam[j];
                float dx = M.x - L.x, dy = M.y + L.y;   // |lam_j - conj(lam_h)|^2
                float e = dx * dx + dy * dy;
                if (e < best) { best = e; bi = j; }
            }
            sbi[tid] = bi;
            float2 c  = C[(d << 6) + tid];
            float2 c2 = C[(d << 6) | bi];
            float chx = 0.5f * (c.x + c2.x);
            float chy = 0.5f * (c.y - c2.y);           // Chat = (C_h + conj(C_hbar))/2
            float2 b = B[(d << 6) + tid];
            float2 p = P[tid];
            float w00x = chx * b.x - chy * b.y, w00y = chx * b.y + chy * b.x;
            float w01x = chx * p.x - chy * p.y, w01y = chx * p.y + chy * p.x;
            float w10x = p.x * b.x + p.y * b.y, w10y = p.x * b.y - p.y * b.x;
            float w11  = p.x * p.x + p.y * p.y;
            tW0[tid] = make_float4(w00x, w00y, w01x, w01y);
            tW1[tid] = make_float4(w10x, w10y, w11, 0.0f);
        }
        __syncthreads();
        // ballots: warps 0,1 fully cover tid<64
        if (tid < HDIM) {
            int bi = sbi[tid];
            unsigned lm = __ballot_sync(0xffffffffu, bi > tid);
            unsigned rm = __ballot_sync(0xffffffffu, bi == tid);
            if ((tid & 31) == 0) { sLm[tid >> 5] = lm; sRm[tid >> 5] = rm; }
        }
        __syncthreads();
        if (tid < HDIM) {
            int lane = tid & 31, w = tid >> 5;
            int bi = sbi[tid];
            unsigned below = (1u << lane) - 1u;
            if (bi > tid) {                    // conj-pair lead
                int slot = __popc(sLm[w] & below) + (w ? __popc(sLm[0]) : 0);
                pA[slot] = tid; pB[slot] = bi;
            } else if (bi == tid) {            // real pole: record rank
                int r = __popc(sRm[w] & below) + (w ? __popc(sRm[0]) : 0);
                realIdx[r] = tid;
            }
        }
        __syncthreads();
        if (tid < HDIM) {
            int bi = sbi[tid];
            if (bi == tid) {
                int lane = tid & 31, w = tid >> 5;
                int r = __popc(sRm[w] & ((1u << lane) - 1u)) + (w ? __popc(sRm[0]) : 0);
                if (!(r & 1)) {                // even-rank real creates the slot
                    int nLead = __popc(sLm[0]) + __popc(sLm[1]);
                    int nReal = __popc(sRm[0]) + __popc(sRm[1]);
                    int slot = nLead + (r >> 1);
                    pA[slot] = tid;
                    pB[slot] = (r + 1 < nReal) ? realIdx[r + 1] : -1;
                }
            }
        }
        __syncthreads();
        // slot parameters
        if (tid < 32) {
            int h1 = pA[tid], h2r = pB[tid];
            int h2 = (h2r >= 0) ? h2r : h1;
            float zf = (h2r >= 0) ? 1.0f : 0.0f;
            float2 u1 = slam[h1], u2 = slam[h2];
            float m = u1.x * u2.x - u1.y * u2.y;
            float n = u1.x + u2.x;
            sMN[tid] = make_float2(m, n);
            float4 a1 = tW0[h1], a2 = tW0[h2];
            float4 b1 = tW1[h1], b2 = tW1[h2];
            float e1_00 = a1.x + zf * a2.x;
            float e0_00 = -(a1.x * u2.x - a1.y * u2.y + zf * (a2.x * u1.x - a2.y * u1.y));
            float e1_01 = a1.z + zf * a2.z;
            float e0_01 = -(a1.z * u2.x - a1.w * u2.y + zf * (a2.z * u1.x - a2.w * u1.y));
            float e1_10 = b1.x + zf * b2.x;
            float e0_10 = -(b1.x * u2.x - b1.y * u2.y + zf * (b2.x * u1.x - b2.y * u1.y));
            float e1_11 = b1.z + zf * b2.z;
            float e0_11 = -(b1.z * u2.x + zf * b2.z * u1.x);
            sE0a[tid] = make_float4(e0_00, e0_00, e0_01, e0_01);
            sE1a[tid] = make_float4(e1_00, e1_00, e1_01, e1_01);
            sE0b[tid] = make_float4(e0_10, e0_10, e0_11, e0_11);
            sE1b[tid] = make_float4(e1_10, e1_10, e1_11, e1_11);
        }
        __syncthreads();

        float delta = __expf(log_delta[d]);
        const float sc = 1.0f / (float)NFFT;       // fold 1/N of inverse FFT
        float dsc = Dp[d] * sc;                    // D*x folded: Kf += D/N at every bin

        // Nyquist bin (z = -1): at = 0.5*delta*sum_h Re(w00) = 0.5*delta*sum_s e1_00
        if (part == 0 && tid == 0) {
            float s = 0.0f;
            #pragma unroll
            for (int q = 0; q < 32; ++q) s += sE1a[q].x;
            g_Kf[(d << 12) + 2048] = make_float2(0.5f * delta * s * sc + dsc, 0.0f);
        }

        // Two points per thread: l0p = part*512 + tid, l1p = l0p + 256
        int l0p = part * 512 + tid;
        int l1p = l0p + 256;
        float mtwo = __fdividef(-2.0f, delta);
        float s0_, c0_, s1_, c1_;
        sincospif((float)l0p * (1.0f / 4096.0f), &s0_, &c0_);
        sincospif((float)l1p * (1.0f / 4096.0f), &s1_, &c1_);
        float th0 = __fdividef(s0_, c0_);
        float th1 = __fdividef(s1_, c1_);
        float G0 = th0 * mtwo, G1 = th1 * mtwo;
        float Gsq0 = G0 * G0,  Gsq1 = G1 * G1;

        u64 P00a = 0ull, P01a = 0ull, P10a = 0ull, P11a = 0ull;
        u64 Q00a = 0ull, Q01a = 0ull, Q10a = 0ull, Q11a = 0ull;
        u64 P00b = 0ull, P01b = 0ull, P10b = 0ull, P11b = 0ull;
        u64 Q00b = 0ull, Q01b = 0ull, Q10b = 0ull, Q11b = 0ull;
        const ulonglong2* pE0a = (const ulonglong2*)sE0a;
        const ulonglong2* pE1a = (const ulonglong2*)sE1a;
        const ulonglong2* pE0b = (const ulonglong2*)sE0b;
        const ulonglong2* pE1b = (const ulonglong2*)sE1b;
        #pragma unroll 8
        for (int s = 0; s < 32; ++s) {
            float2 mn = sMN[s];
            ulonglong2 E0A = pE0a[s];
            ulonglong2 E1A = pE1a[s];
            ulonglong2 E0B = pE0b[s];
            ulonglong2 E1B = pE1b[s];
            // point 0
            {
                float dx  = mn.x - Gsq0;
                float dyn = mn.y * G0;
                float den = fmaf(dx, dx, dyn * dyn);
                float im  = __fdividef(1.0f, den);
                u64 t = pk2(dx * im, dyn * im);
                P00a = fma2(E0A.x, t, P00a); Q00a = fma2(E1A.x, t, Q00a);
                P01a = fma2(E0A.y, t, P01a); Q01a = fma2(E1A.y, t, Q01a);
                P10a = fma2(E0B.x, t, P10a); Q10a = fma2(E1B.x, t, Q10a);
                P11a = fma2(E0B.y, t, P11a); Q11a = fma2(E1B.y, t, Q11a);
            }
            // point 1
            {
                float dx  = mn.x - Gsq1;
                float dyn = mn.y * G1;
                float den = fmaf(dx, dx, dyn * dyn);
                float im  = __fdividef(1.0f, den);
                u64 t = pk2(dx * im, dyn * im);
                P00b = fma2(E0A.x, t, P00b); Q00b = fma2(E1A.x, t, Q00b);
                P01b = fma2(E0A.y, t, P01b); Q01b = fma2(E1A.y, t, Q01b);
                P10b = fma2(E0B.x, t, P10b); Q10b = fma2(E1B.x, t, Q10b);
                P11b = fma2(E0B.y, t, P11b); Q11b = fma2(E1B.y, t, Q11b);
            }
        }

        // epilogue per point: s = P + iG*Q, Woodbury, 2/u = 1 - i*th, scale
        #pragma unroll
        for (int k = 0; k < 2; ++k) {
            float G  = k ? G1 : G0;
            float th = k ? th1 : th0;
            int   l  = k ? l1p : l0p;
            u64 uP00 = k ? P00b : P00a, uQ00 = k ? Q00b : Q00a;
            u64 uP01 = k ? P01b : P01a, uQ01 = k ? Q01b : Q01a;
            u64 uP10 = k ? P10b : P10a, uQ10 = k ? Q10b : Q10a;
            u64 uP11 = k ? P11b : P11a, uQ11 = k ? Q11b : Q11a;
            float px, py, qx, qy;
            upk2(uP00, px, py); upk2(uQ00, qx, qy);
            float s00x = px - G * qy, s00y = py + G * qx;
            upk2(uP01, px, py); upk2(uQ01, qx, qy);
            float s01x = px - G * qy, s01y = py + G * qx;
            upk2(uP10, px, py); upk2(uQ10, qx, qy);
            float s10x = px - G * qy, s10y = py + G * qx;
            upk2(uP11, px, py); upk2(uQ11, qx, qy);
            float s11x = px - G * qy, s11y = py + G * qx;

            float nx  = s01x * s10x - s01y * s10y;
            float ny  = s01x * s10y + s01y * s10x;
            float dnx = 1.0f + s11x, dny = s11y;
            float ddi = __fdividef(1.0f, dnx * dnx + dny * dny);
            float cx  = (nx * dnx + ny * dny) * ddi;
            float cy  = (ny * dnx - nx * dny) * ddi;
            float k0x = s00x - cx, k0y = s00y - cy;
            float ax = k0x + th * k0y;
            float ay = k0y - th * k0x;
            ax = ax * sc + dsc; ay *= sc;
            if (l == 0) ay = 0.0f;
            g_Kf[(d << 12) + l] = make_float2(ax, ay);
            if (l > 0)
                g_Kf[(d << 12) + (NFFT - l)] = make_float2(ax, -ay);
        }
    } else if (blockIdx.x < 3072) {
        // -------- t1 path: 32d x 64l tiles, MLP=4 --------
        int m  = blockIdx.x - 1024;                // [0, 2048)
        int b4 = m >> 9;
        int lblk = (m >> 3) & 63;
        int dblk = m & 7;
        int d0 = dblk << 5, l0 = lblk << 6;
        const float4* x4 = (const float4*)x;
        float4 A[2], Bv[2];
        #pragma unroll
        for (int u = 0; u < 2; ++u) {
            int mm = tid + (u << 8);               // [0, 512)
            int l = mm >> 3, d4 = mm & 7;
            int base0 = ((b4 * NFFT) + l0 + l) * (DDIM / 4) + (d0 >> 2) + d4;
            A[u]  = x4[base0];
            Bv[u] = x4[base0 + 4 * NFFT * (DDIM / 4)];
        }
        #pragma unroll
        for (int u = 0; u < 2; ++u) {
            int mm = tid + (u << 8);
            int l = mm >> 3, d4 = mm & 7;
            tile[l][4 * d4 + 0] = make_float2(A[u].x, Bv[u].x);
            tile[l][4 * d4 + 1] = make_float2(A[u].y, Bv[u].y);
            tile[l][4 * d4 + 2] = make_float2(A[u].z, Bv[u].z);
            tile[l][4 * d4 + 3] = make_float2(A[u].w, Bv[u].w);
        }
        __syncthreads();
        float4* zT4 = (float4*)g_zT;
        #pragma unroll
        for (int u = 0; u < 4; ++u) {
            int mm = tid + (u << 8);               // [0, 1024)
            int dd = mm >> 5, lp = mm & 31;
            float2 t0 = tile[2 * lp][dd];
            float2 t1 = tile[2 * lp + 1][dd];
            zT4[(((b4 * DDIM) + d0 + dd) * NFFT + l0 + 2 * lp) >> 1]
                = make_float4(t0.x, t0.y, t1.x, t1.y);
        }
    } else {
        // -------- twiddle table (used by the NEXT launch only) --------
        int k = (blockIdx.x - 3072) * 256 + tid;
        double ang = -6.283185307179586476925286766559 * (double)k / (double)NFFT;
        g_tw[k] = make_float2((float)cos(ang), (float)sin(ang));
    }
}

// ---------------- radix-8 Stockham FFT helpers ----------------
__device__ __forceinline__ float2 cmulf(float2 a, float2 b) {
    return make_float2(a.x * b.x - a.y * b.y, a.x * b.y + a.y * b.x);
}
#define SWZ(m) ((m) ^ (((m) >> 4) & 7))

template<int DIR>
__device__ __forceinline__ void bfly8(float2 a[8]) {
    const float S2 = 0.70710678118654752440f;
    float2 b0, b1, b2, b3, c0, c1, c2, c3;
    b0.x=a[0].x+a[4].x; b0.y=a[0].y+a[4].y;  c0.x=a[0].x-a[4].x; c0.y=a[0].y-a[4].y;
    b1.x=a[1].x+a[5].x; b1.y=a[1].y+a[5].y;  c1.x=a[1].x-a[5].x; c1.y=a[1].y-a[5].y;
    b2.x=a[2].x+a[6].x; b2.y=a[2].y+a[6].y;  c2.x=a[2].x-a[6].x; c2.y=a[2].y-a[6].y;
    b3.x=a[3].x+a[7].x; b3.y=a[3].y+a[7].y;  c3.x=a[3].x-a[7].x; c3.y=a[3].y-a[7].y;
    float2 tc1, tc2, tc3;
    if (DIR > 0) {
        tc1 = make_float2(S2 * (c1.x + c1.y),  S2 * (c1.y - c1.x));
        tc2 = make_float2(c2.y, -c2.x);
        tc3 = make_float2(S2 * (c3.y - c3.x), -S2 * (c3.x + c3.y));
    } else {
        tc1 = make_float2(S2 * (c1.x - c1.y),  S2 * (c1.y + c1.x));
        tc2 = make_float2(-c2.y, c2.x);
        tc3 = make_float2(-S2 * (c3.x + c3.y), S2 * (c3.x - c3.y));
    }
    float2 p0 = make_float2(b0.x + b2.x, b0.y + b2.y);
    float2 p1 = make_float2(b0.x - b2.x, b0.y - b2.y);
    float2 p2 = make_float2(b1.x + b3.x, b1.y + b3.y);
    float2 p3 = make_float2(b1.x - b3.x, b1.y - b3.y);
    float2 q0 = make_float2(c0.x + tc2.x, c0.y + tc2.y);
    float2 q1 = make_float2(c0.x - tc2.x, c0.y - tc2.y);
    float2 q2 = make_float2(tc1.x + tc3.x, tc1.y + tc3.y);
    float2 q3 = make_float2(tc1.x - tc3.x, tc1.y - tc3.y);
    float2 jp3 = (DIR > 0) ? make_float2(p3.y, -p3.x) : make_float2(-p3.y, p3.x);
    float2 jq3 = (DIR > 0) ? make_float2(q3.y, -q3.x) : make_float2(-q3.y, q3.x);
    a[0] = make_float2(p0.x + p2.x, p0.y + p2.y);
    a[4] = make_float2(p0.x - p2.x, p0.y - p2.y);
    a[2] = make_float2(p1.x + jp3.x, p1.y + jp3.y);
    a[6] = make_float2(p1.x - jp3.x, p1.y - jp3.y);
    a[1] = make_float2(q0.x + q2.x, q0.y + q2.y);
    a[5] = make_float2(q0.x - q2.x, q0.y - q2.y);
    a[3] = make_float2(q1.x + jq3.x, q1.y + jq3.y);
    a[7] = make_float2(q1.x - jq3.x, q1.y - jq3.y);
}

// twiddle via single load + power chain (log depth): w^k, k=1..7
template<int DIR, int TSH>
__device__ __forceinline__ void stage_tw_store(float2* dst, float2 a[8], int i) {
    const int s = 1 << TSH;
    int ps = (i >> TSH) << TSH;
    if (TSH < 9) {
        float2 w1 = g_tw[ps];
        if (DIR < 0) w1.y = -w1.y;
        float2 w2 = cmulf(w1, w1);
        float2 w3 = cmulf(w2, w1);
        float2 w4 = cmulf(w2, w2);
        float2 w5 = cmulf(w3, w2);
        float2 w6 = cmulf(w3, w3);
        float2 w7 = cmulf(w4, w3);
        a[1] = cmulf(a[1], w1);
        a[2] = cmulf(a[2], w2);
        a[3] = cmulf(a[3], w3);
        a[4] = cmulf(a[4], w4);
        a[5] = cmulf(a[5], w5);
        a[6] = cmulf(a[6], w6);
        a[7] = cmulf(a[7], w7);
    }
    int base = (i & (s - 1)) + (ps << 3);
    #pragma unroll
    for (int k = 0; k < 8; ++k) dst[SWZ(base + (k << TSH))] = a[k];
}

__global__ __launch_bounds__(512, 2) void fft_conv8_kernel() {
    extern __shared__ float2 sm[];
    float2* S0 = sm;
    float2* S1 = sm + NFFT;
    int d  = blockIdx.x & (DDIM - 1);
    int i  = threadIdx.x;
    float2* sig = g_zT + (size_t)blockIdx.x * NFFT;
    float2 a[8];

    // ---- forward ----
    #pragma unroll
    for (int j = 0; j < 8; ++j) a[j] = sig[i + j * 512];
    bfly8<1>(a); stage_tw_store<1, 0>(S0, a, i);
    __syncthreads();
    #pragma unroll
    for (int j = 0; j < 8; ++j) a[j] = S0[SWZ(i + j * 512)];
    bfly8<1>(a); stage_tw_store<1, 3>(S1, a, i);
    __syncthreads();
    #pragma unroll
    for (int j = 0; j < 8; ++j) a[j] = S1[SWZ(i + j * 512)];
    bfly8<1>(a); stage_tw_store<1, 6>(S0, a, i);
    __syncthreads();
    #pragma unroll
    for (int j = 0; j < 8; ++j) a[j] = S0[SWZ(i + j * 512)];
    bfly8<1>(a);
    // F3 (TSH=9): no twiddles; a[j] IS natural-order bin (i + j*512).
    {
        const float2* kf = g_Kf + (d << 12);
        #pragma unroll
        for (int j = 0; j < 8; ++j) a[j] = cmulf(a[j], __ldg(&kf[i + j * 512]));
    }
    // ---- inverse ----
    bfly8<-1>(a); stage_tw_store<-1, 0>(S1, a, i);
    __syncthreads();
    #pragma unroll
    for (int j = 0; j < 8; ++j) a[j] = S1[SWZ(i + j * 512)];
    bfly8<-1>(a); stage_tw_store<-1, 3>(S0, a, i);
    __syncthreads();
    #pragma unroll
    for (int j = 0; j < 8; ++j) a[j] = S0[SWZ(i + j * 512)];
    bfly8<-1>(a); stage_tw_store<-1, 6>(S1, a, i);
    __syncthreads();
    #pragma unroll
    for (int j = 0; j < 8; ++j) a[j] = S1[SWZ(i + j * 512)];
    bfly8<-1>(a);
    #pragma unroll
    for (int k = 0; k < 8; ++k) sig[i + k * 512] = a[k];
}

// ---------------- untranspose + split Re/Im (32d x 64l tiles, MLP=4) --------
__global__ __launch_bounds__(256) void t2_kernel(float* __restrict__ y) {
    __shared__ float2 tile[32][65];
    int b4 = blockIdx.z;
    int d0 = blockIdx.x << 5;
    int l0 = blockIdx.y << 6;
    int tid = threadIdx.x;
    const float4* zT4 = (const float4*)g_zT;
    #pragma unroll
    for (int u = 0; u < 4; ++u) {
        int m = tid + (u << 8);
        int dd = m >> 5, lp = m & 31;
        float4 v = zT4[(((b4 * DDIM) + d0 + dd) * NFFT + l0 + 2 * lp) >> 1];
        tile[dd][2 * lp]     = make_float2(v.x, v.y);
        tile[dd][2 * lp + 1] = make_float2(v.z, v.w);
    }
    __syncthreads();
    float4* y4 = (float4*)y;
    #pragma unroll
    for (int u = 0; u < 4; ++u) {
        int m = tid + (u << 8);
        int k = m & 7, l = (m >> 3) & 63;
        int plane = m >> 9;                        // u<2 -> 0 (Re), u>=2 -> 1 (Im)
        float2 t0 = tile[4 * k + 0][l];
        float2 t1 = tile[4 * k + 1][l];
        float2 t2 = tile[4 * k + 2][l];
        float2 t3 = tile[4 * k + 3][l];
        int row = ((b4 + plane * 4) * NFFT + l0 + l) * (DDIM / 4) + (d0 >> 2) + k;
        y4[row] = plane ? make_float4(t0.y, t1.y, t2.y, t3.y)
                        : make_float4(t0.x, t1.x, t2.x, t3.x);
    }
}

// ---------------- launcher ----------------
extern "C" void kernel_launch(void* const* d_in, const int* in_sizes, int n_in,
                              void* d_out, int out_size) {
    const float*  x   = (const float*)d_in[0];
    const float2* lam = (const float2*)d_in[1];
    const float2* P   = (const float2*)d_in[2];
    const float2* B   = (const float2*)d_in[3];
    const float2* C   = (const float2*)d_in[4];
    const float*  Dp  = (const float*)d_in[5];
    const float*  ld  = (const float*)d_in[6];
    float* y = (float*)d_out;

    cudaFuncSetAttribute(fft_conv8_kernel,
                         cudaFuncAttributeMaxDynamicSharedMemorySize,
                         2 * NFFT * sizeof(float2));

    kf_t1_kernel<<<1024 + 2048 + 16, 256>>>(x, lam, P, B, C, ld, Dp);
    fft_conv8_kernel<<<NB4 * DDIM, 512, 2 * NFFT * sizeof(float2)>>>();
    t2_kernel<<<dim3(DDIM / 32, NFFT / 64, NB4), dim3(256)>>>(y);
}